// round 10
// baseline (speedup 1.0000x reference)
#include <cuda_runtime.h>
#include <cuda_bf16.h>
#include <math.h>
#include <stdint.h>

#define BB 2
#define SS 2048
#define DD 1024
#define NH 16
#define NKV 4
#define HD 64
#define GATE_CH 12
#define EPSV 1e-6f
#define QKVLD 1536   // qkv buffer row stride: [q(1024) | k(256) | v(256)]

// ---------------- device scratch (allocation-free rule) ----------------
__device__ float    g_qkv[BB * SS * QKVLD];     // fp32 qkv (row-major)
__device__ float    g_y[BB * SS * DD];          // attention output (row-major)
__device__ float    g_xa[(size_t)32 * 64 * 2048];    // x, fragment-major A tiles
__device__ float    g_ya[(size_t)32 * 64 * 2048];    // y, fragment-major A tiles
__device__ float    g_wqkvT[(size_t)12 * 64 * 2048]; // Wq|Wk|Wv, fragment-major B tiles
__device__ float    g_woT[(size_t)8 * 64 * 2048];    // Wo, fragment-major B tiles
__device__ uint32_t g_qpk[BB * SS * NH * 64];   // q packed bf16 hi|lo
__device__ uint32_t g_kpk[BB * SS * NKV * 64];  // k packed bf16 hi|lo

// ---------------- helpers ----------------
__device__ __forceinline__ float to_tf32(float x) {
    float r; asm("cvt.rna.tf32.f32 %0, %1;" : "=f"(r) : "f"(x)); return r;
}
__device__ __forceinline__ uint32_t pack_bf16(float e, float o) {
    uint16_t a = __bfloat16_as_ushort(__float2bfloat16(e));
    uint16_t b = __bfloat16_as_ushort(__float2bfloat16(o));
    return ((uint32_t)b << 16) | a;
}
__device__ __forceinline__ void mma_tf32(float* d, const uint32_t* a, const uint32_t* b) {
    asm volatile(
        "mma.sync.aligned.m16n8k8.row.col.f32.tf32.tf32.f32 "
        "{%0,%1,%2,%3}, {%4,%5,%6,%7}, {%8,%9}, {%0,%1,%2,%3};\n"
        : "+f"(d[0]), "+f"(d[1]), "+f"(d[2]), "+f"(d[3])
        : "r"(a[0]), "r"(a[1]), "r"(a[2]), "r"(a[3]), "r"(b[0]), "r"(b[1]));
}
__device__ __forceinline__ void mma_bf16(float* d, const uint32_t* a, const uint32_t* b) {
    asm volatile(
        "mma.sync.aligned.m16n8k16.row.col.f32.bf16.bf16.f32 "
        "{%0,%1,%2,%3}, {%4,%5,%6,%7}, {%8,%9}, {%0,%1,%2,%3};\n"
        : "+f"(d[0]), "+f"(d[1]), "+f"(d[2]), "+f"(d[3])
        : "r"(a[0]), "r"(a[1]), "r"(a[2]), "r"(a[3]), "r"(b[0]), "r"(b[1]));
}
__device__ __forceinline__ void cp_async16(uint32_t saddr, const void* gptr) {
    asm volatile("cp.async.cg.shared.global [%0], [%1], 16;" :: "r"(saddr), "l"(gptr));
}
#define CP_COMMIT() asm volatile("cp.async.commit_group;")
#define CP_WAIT(n)  asm volatile("cp.async.wait_group %0;" :: "n"(n))

// ---------------------------------------------------------------------------
// pack_a: row-major [M][1024] fp32 -> fragment-major A tiles (tf32-rounded).
// tile(rt,kt) = 2048 floats; quad q = (g*8+b)*32 + lane, holds
// [r][k], [r+8][k], [r][k+4], [r+8][k+4], r = rt*128+b*16+gid, k = kt*16+g*8+tig
// grid (64, M/128), block 256
// ---------------------------------------------------------------------------
__global__ void pack_a(const float* __restrict__ src, float* __restrict__ dst)
{
    int kt = blockIdx.x, rt = blockIdx.y;
    float* dtile = dst + ((size_t)rt * 64 + kt) * 2048;
    const float* s = src + (size_t)rt * 128 * 1024 + kt * 16;
    for (int q = threadIdx.x; q < 512; q += 256) {
        int gb = q >> 5;
        int g = gb >> 3, b = gb & 7;
        int lane = q & 31;
        int gid = lane >> 2, tig = lane & 3;
        const float* p = s + (size_t)(b * 16 + gid) * 1024 + g * 8 + tig;
        float4 v;
        v.x = to_tf32(p[0]);
        v.y = to_tf32(p[8 * 1024]);
        v.z = to_tf32(p[4]);
        v.w = to_tf32(p[8 * 1024 + 4]);
        *(float4*)(dtile + q * 4) = v;
    }
}

// ---------------------------------------------------------------------------
// pack_b: W[K][n_src] row-major -> fragment-major B tiles at col-tile ct0+cl.
// tile = 2048 floats: plane(2) x (g*4+w)(8) x lane(32) x 4(ni).
// plane0: k = kt*16+g*8+tig; plane1: k+4. value[ni] = W[k][cl*128+w*32+ni*8+gid]
// grid (64, n_src/128), block 256
// ---------------------------------------------------------------------------
__global__ void pack_b(const float* __restrict__ W, float* __restrict__ dst,
                       int n_src, int ct0)
{
    int kt = blockIdx.x, cl = blockIdx.y;
    float* dtile = dst + ((size_t)(ct0 + cl) * 64 + kt) * 2048;
    const float* s = W + (size_t)kt * 16 * n_src + cl * 128;
    for (int q = threadIdx.x; q < 512; q += 256) {
        int plane = q >> 8;
        int q8 = q & 255;
        int gw = q8 >> 5;
        int g = gw >> 2, w = gw & 3;
        int lane = q8 & 31;
        int gid = lane >> 2, tig = lane & 3;
        const float* p = s + (size_t)(g * 8 + tig + plane * 4) * n_src + w * 32 + gid;
        float4 v;
        v.x = to_tf32(p[0]);
        v.y = to_tf32(p[8]);
        v.z = to_tf32(p[16]);
        v.w = to_tf32(p[24]);
        *(float4*)(dtile + q * 4) = v;
    }
}

// ---------------------------------------------------------------------------
// gemm_fm: tf32 HMMA GEMM on fragment-major tiles, 3-stage cp.async.
// CTA 128x128, BK=16, 256 thr, warp tile 64x32. All fragment loads are LDS.128.
// dyn smem: 3 stages x (A 8KB | B 8KB) = 49152 B
// ---------------------------------------------------------------------------
#define GFM_SMEM 49152
__global__ __launch_bounds__(256, 2) void gemm_fm(
    const float* __restrict__ At, const float* __restrict__ Bt,
    float* __restrict__ C, int nkt, int ldc)
{
    extern __shared__ float smg[];
    uint32_t smb = (uint32_t)__cvta_generic_to_shared(smg);
    const int tid = threadIdx.x;
    const int lane = tid & 31, wid = tid >> 5;
    const int gid = lane >> 2, tig = lane & 3;
    const int wm4 = (wid >> 2) * 4;     // warp_m / 16
    const int wn5 = wid & 3;            // warp_n / 32
    const int rowBase = blockIdx.y * 128, colBase = blockIdx.x * 128;

    const float* Abase = At + (size_t)blockIdx.y * nkt * 2048 + tid * 8;
    const float* Bbase = Bt + (size_t)blockIdx.x * nkt * 2048 + tid * 8;

#define FM_STAGE(c, s) do { \
    uint32_t _d = smb + (s) * 16384 + tid * 32; \
    const float* _a = Abase + (size_t)(c) * 2048; \
    const float* _b = Bbase + (size_t)(c) * 2048; \
    cp_async16(_d, _a);            cp_async16(_d + 16, _a + 4); \
    cp_async16(_d + 8192, _b);     cp_async16(_d + 8192 + 16, _b + 4); \
    CP_COMMIT(); \
} while (0)

    FM_STAGE(0, 0);
    FM_STAGE(1, 1);

    float acc[4][4][4] = {};
    for (int it = 0; it < nkt; it++) {
        const int s = it % 3;
        __syncthreads();                       // compute(it-1) done before restage
        if (it + 2 < nkt) {
            FM_STAGE(it + 2, (it + 2) % 3);
            CP_WAIT(2);
        } else if (it + 1 < nkt) {
            CP_WAIT(1);
        } else {
            CP_WAIT(0);
        }
        __syncthreads();                       // staged data visible

        const uint4* As4 = (const uint4*)(smg + s * 4096);
        const uint4* Bs4 = As4 + 512;
#pragma unroll
        for (int g = 0; g < 2; g++) {
            uint4 afr[4];
#pragma unroll
            for (int mi = 0; mi < 4; mi++)
                afr[mi] = As4[(g * 8 + wm4 + mi) * 32 + lane];
            uint4 b0 = Bs4[(g * 4 + wn5) * 32 + lane];
            uint4 b1 = Bs4[256 + (g * 4 + wn5) * 32 + lane];
            uint32_t bf[4][2] = {
                {b0.x, b1.x}, {b0.y, b1.y}, {b0.z, b1.z}, {b0.w, b1.w}};
#pragma unroll
            for (int mi = 0; mi < 4; mi++) {
                const uint32_t* af = (const uint32_t*)&afr[mi];
#pragma unroll
                for (int ni = 0; ni < 4; ni++)
                    mma_tf32(acc[mi][ni], af, bf[ni]);
            }
        }
    }

    const int warp_m = wm4 * 16, warp_n = wn5 * 32;
#pragma unroll
    for (int mi = 0; mi < 4; mi++) {
#pragma unroll
        for (int ni = 0; ni < 4; ni++) {
            int row = rowBase + warp_m + mi * 16 + gid;
            int col = colBase + warp_n + ni * 8 + 2 * tig;
            *(float2*)(C + (size_t)row * ldc + col) =
                make_float2(acc[mi][ni][0], acc[mi][ni][1]);
            *(float2*)(C + (size_t)(row + 8) * ldc + col) =
                make_float2(acc[mi][ni][2], acc[mi][ni][3]);
        }
    }
}

// ---------------------------------------------------------------------------
// Fused prep: hh in [0,20) -> RoPE+RMSNorm q/k (packed bf16 hi/lo);
//             hh in [20,24) -> v gate (+ tf32 round). grid = B*S*24, block 64
// ---------------------------------------------------------------------------
__global__ void prep_kernel(const float* __restrict__ cosp,
                            const float* __restrict__ sinp,
                            const float* __restrict__ x,
                            const float* __restrict__ ve,
                            const float* __restrict__ Wg)
{
    int blk = blockIdx.x;
    int hh = blk % (NH + NKV + NKV);
    int bs = blk / (NH + NKV + NKV);
    int d = threadIdx.x;

    if (hh >= NH + NKV) {
        int kvh = hh - (NH + NKV);
        const float* xr = x + (size_t)bs * DD;
        float g = 0.f;
#pragma unroll
        for (int c = 0; c < GATE_CH; c++) g += xr[c] * Wg[c * NKV + kvh];
        g = 3.f / (1.f + __expf(-g));
        float* vp = &g_qkv[(size_t)bs * QKVLD + 1280 + kvh * HD + d];
        *vp = to_tf32(*vp + g * ve[(size_t)bs * (NKV * HD) + kvh * HD + d]);
        return;
    }

    int s = bs % SS;
    const float* ptr = g_qkv + (size_t)bs * QKVLD +
                       ((hh < NH) ? hh * HD : 1024 + (hh - NH) * HD);

    int half = d & 31;
    float c  = cosp[s * 32 + half];
    float sn = sinp[s * 32 + half];
    float x1 = ptr[half];
    float x2 = ptr[half + 32];
    float rot = (d < 32) ? (x1 * c + x2 * sn) : (-x1 * sn + x2 * c);

    __shared__ float red[2];
    float v = rot * rot;
#pragma unroll
    for (int o = 16; o > 0; o >>= 1) v += __shfl_xor_sync(0xffffffffu, v, o);
    if ((d & 31) == 0) red[d >> 5] = v;
    __syncthreads();
    float total = red[0] + red[1];
    float r = rsqrtf(total * (1.f / HD) + EPSV) * 1.2f;
    float val = rot * r;
    if (hh < NH) val *= 0.125f;

    float hif = __bfloat162float(__float2bfloat16(val));
    float lof = val - hif;
    float val_o = __shfl_down_sync(0xffffffffu, val, 1);
    float lof_o = __shfl_down_sync(0xffffffffu, lof, 1);

    if ((d & 1) == 0) {
        uint32_t hp = pack_bf16(val, val_o);
        uint32_t lp = pack_bf16(lof, lof_o);
        uint32_t* out = (hh < NH)
            ? &g_qpk[((size_t)bs * NH + hh) * 64]
            : &g_kpk[((size_t)bs * NKV + (hh - NH)) * 64];
        out[d >> 1]        = hp;
        out[32 + (d >> 1)] = lp;
    }
}

// ---------------------------------------------------------------------------
// Tensor-core flash attention, 128 queries/CTA, 8 warps (unchanged from R9).
// ---------------------------------------------------------------------------
#define ATS 68
#define TILEF (64 * ATS)
__global__ __launch_bounds__(256, 2) void attn_tc(const int* __restrict__ winp)
{
    const int win = *winp;
    int bid = blockIdx.x;
    int qt = bid & 15;
    int bh = bid >> 4;
    int h = bh % NH;
    int b = bh / NH;
    int q0 = qt * 128;
    int kvh = h / (NH / NKV);

    const int tid = threadIdx.x;
    const int lane = tid & 31;
    const int warp = tid >> 5;
    const int wrow = warp * 16;
    const int gid = lane >> 2;
    const int tig = lane & 3;

    extern __shared__ float sm[];
    uint32_t* Khl0 = (uint32_t*)sm;
    float* Ss   = sm + 4 * TILEF;
    float* scb  = sm + 4 * TILEF + 128 * ATS;
    float* lbuf = scb + 128;
    uint32_t smbase = (uint32_t)__cvta_generic_to_shared(sm);

    const int st_r  = tid >> 4;
    const int st_c4 = (tid & 15) * 4;

    {
        uint32_t* Qs = (uint32_t*)Ss;
        for (int i = tid; i < 128 * 16; i += 256) {
            int r = i >> 4;
            int c4 = (i & 15) * 4;
            *(uint4*)&Qs[r * ATS + c4] =
                *(const uint4*)(g_qpk + ((size_t)(b * SS + q0 + r) * NH + h) * 64 + c4);
        }
    }
    __syncthreads();

    uint32_t ahi[4][4], alo[4][4];
    {
        const uint32_t* Qs = (const uint32_t*)Ss;
#pragma unroll
        for (int ks = 0; ks < 4; ks++) {
            int cb = ks * 8 + tig;
            ahi[ks][0] = Qs[(wrow + gid) * ATS + cb];
            ahi[ks][1] = Qs[(wrow + gid + 8) * ATS + cb];
            ahi[ks][2] = Qs[(wrow + gid) * ATS + cb + 4];
            ahi[ks][3] = Qs[(wrow + gid + 8) * ATS + cb + 4];
            alo[ks][0] = Qs[(wrow + gid) * ATS + 32 + cb];
            alo[ks][1] = Qs[(wrow + gid + 8) * ATS + 32 + cb];
            alo[ks][2] = Qs[(wrow + gid) * ATS + 32 + cb + 4];
            alo[ks][3] = Qs[(wrow + gid + 8) * ATS + 32 + cb + 4];
        }
    }

    float m = -1e30f, lsum = 0.f;
    float oacc[8][4] = {};

    int kmin = q0 - win + 1;
    if (kmin < 0) kmin = 0;
    int t0 = kmin >> 6;
    int t1 = (q0 + 127) >> 6;

    {
        int kb = t0 << 6;
        const uint32_t* ksrc = g_kpk + ((size_t)(b * SS + kb + st_r) * NKV + kvh) * 64 + st_c4;
        const float* vsrc = g_qkv + (size_t)(b * SS + kb + st_r) * QKVLD + 1280 + kvh * HD + st_c4;
        uint32_t kdst = smbase + (0 * TILEF + st_r * ATS + st_c4) * 4;
        uint32_t vdst = smbase + (2 * TILEF + st_r * ATS + st_c4) * 4;
#pragma unroll
        for (int j = 0; j < 4; j++) {
            cp_async16(kdst + j * 16 * ATS * 4, ksrc + (size_t)j * 16 * NKV * 64);
            cp_async16(vdst + j * 16 * ATS * 4, vsrc + (size_t)j * 16 * QKVLD);
        }
        CP_COMMIT();
    }

    for (int t = t0; t <= t1; t++) {
        int kb = t << 6;
        const int buf = (t - t0) & 1;
        __syncthreads();
        if (t < t1) {
            int nb = (t + 1) << 6;
            const uint32_t* ksrc = g_kpk + ((size_t)(b * SS + nb + st_r) * NKV + kvh) * 64 + st_c4;
            const float* vsrc = g_qkv + (size_t)(b * SS + nb + st_r) * QKVLD + 1280 + kvh * HD + st_c4;
            uint32_t kdst = smbase + ((buf ^ 1) * TILEF + st_r * ATS + st_c4) * 4;
            uint32_t vdst = smbase + ((2 + (buf ^ 1)) * TILEF + st_r * ATS + st_c4) * 4;
#pragma unroll
            for (int j = 0; j < 4; j++) {
                cp_async16(kdst + j * 16 * ATS * 4, ksrc + (size_t)j * 16 * NKV * 64);
                cp_async16(vdst + j * 16 * ATS * 4, vsrc + (size_t)j * 16 * QKVLD);
            }
            CP_COMMIT();
            CP_WAIT(1);
        } else {
            CP_WAIT(0);
        }
        __syncthreads();

        bool active = (kb <= q0 + wrow + 15) && (kb + 63 >= q0 + wrow - win + 1);
        if (active) {
            const uint32_t* Khl = Khl0 + buf * TILEF;
            const float* Vs = sm + (2 + buf) * TILEF;

            float accS[8][4] = {};
#pragma unroll
            for (int ks = 0; ks < 4; ks++) {
#pragma unroll
                for (int ni = 0; ni < 8; ni++) {
                    const uint32_t* kr = &Khl[(ni * 8 + gid) * ATS + ks * 8 + tig];
                    uint32_t bh2[2] = { kr[0],  kr[4] };
                    uint32_t bl2[2] = { kr[32], kr[36] };
                    mma_bf16(accS[ni], ahi[ks], bh2);
                    mma_bf16(accS[ni], alo[ks], bh2);
                    mma_bf16(accS[ni], ahi[ks], bl2);
                }
            }

#pragma unroll
            for (int ni = 0; ni < 8; ni++) {
#pragma unroll
                for (int j = 0; j < 4; j++) {
                    int col = ni * 8 + 2 * tig + (j & 1);
                    int r = gid + ((j >> 1) << 3);
                    int qpos = q0 + wrow + r;
                    int kpos = kb + col;
                    bool ok = (kpos <= qpos) && (kpos >= qpos - win + 1);
                    Ss[(wrow + r) * ATS + col] = ok ? accS[ni][j] : -1e30f;
                }
            }
            __syncwarp();

            {
                int srow = lane >> 1;
                int cb = (lane & 1) * 32;
                float* sp = &Ss[(wrow + srow) * ATS + cb];
                float rmax = -1e30f;
#pragma unroll
                for (int c = 0; c < 32; c++) rmax = fmaxf(rmax, sp[c]);
                rmax = fmaxf(rmax, __shfl_xor_sync(0xffffffffu, rmax, 1));
                float mnew = fmaxf(m, rmax);
                float scale, rs = 0.f;
                if (mnew <= -1e20f) {
                    scale = 1.f;
#pragma unroll
                    for (int c = 0; c < 32; c++) sp[c] = 0.f;
                } else {
                    scale = __expf(m - mnew);
#pragma unroll
                    for (int c = 0; c < 32; c++) {
                        float p = __expf(sp[c] - mnew);
                        rs += p;
                        sp[c] = to_tf32(p);
                    }
                }
                m = mnew;
                rs += __shfl_xor_sync(0xffffffffu, rs, 1);
                lsum = lsum * scale + rs;
                if ((lane & 1) == 0) scb[wrow + srow] = scale;
            }
            __syncwarp();

            {
                float sc0 = scb[wrow + gid];
                float sc1 = scb[wrow + gid + 8];
#pragma unroll
                for (int ni = 0; ni < 8; ni++) {
                    oacc[ni][0] *= sc0; oacc[ni][1] *= sc0;
                    oacc[ni][2] *= sc1; oacc[ni][3] *= sc1;
                }
            }
#pragma unroll
            for (int ks = 0; ks < 8; ks++) {
                uint32_t pa[4];
                pa[0] = __float_as_uint(Ss[(wrow + gid) * ATS + ks * 8 + tig]);
                pa[1] = __float_as_uint(Ss[(wrow + gid + 8) * ATS + ks * 8 + tig]);
                pa[2] = __float_as_uint(Ss[(wrow + gid) * ATS + ks * 8 + tig + 4]);
                pa[3] = __float_as_uint(Ss[(wrow + gid + 8) * ATS + ks * 8 + tig + 4]);
#pragma unroll
                for (int ni = 0; ni < 8; ni++) {
                    uint32_t vb[2];
                    vb[0] = __float_as_uint(Vs[(ks * 8 + tig) * ATS + ni * 8 + gid]);
                    vb[1] = __float_as_uint(Vs[(ks * 8 + tig + 4) * ATS + ni * 8 + gid]);
                    mma_tf32(oacc[ni], pa, vb);
                }
            }
        }
    }

    if ((lane & 1) == 0) lbuf[wrow + (lane >> 1)] = lsum;
    __syncwarp();
    float li0 = 1.f / lbuf[wrow + gid];
    float li1 = 1.f / lbuf[wrow + gid + 8];

#pragma unroll
    for (int ni = 0; ni < 8; ni++) {
        int col = h * HD + ni * 8 + 2 * tig;
        int row0 = b * SS + q0 + wrow + gid;
        *(float2*)(g_y + (size_t)row0 * DD + col) =
            make_float2(to_tf32(oacc[ni][0] * li0), to_tf32(oacc[ni][1] * li0));
        *(float2*)(g_y + (size_t)(row0 + 8) * DD + col) =
            make_float2(to_tf32(oacc[ni][2] * li1), to_tf32(oacc[ni][3] * li1));
    }
}

// ---------------------------------------------------------------------------
extern "C" void kernel_launch(void* const* d_in, const int* in_sizes, int n_in,
                              void* d_out, int out_size)
{
    const float* x    = (const float*)d_in[0];
    const float* ve   = (const float*)d_in[1];
    const float* cosp = (const float*)d_in[2];
    const float* sinp = (const float*)d_in[3];
    const float* Wq   = (const float*)d_in[4];
    const float* Wk   = (const float*)d_in[5];
    const float* Wv   = (const float*)d_in[6];
    const float* Wo   = (const float*)d_in[7];
    const float* Wg   = (const float*)d_in[8];
    const int*   win  = (const int*)d_in[9];
    float* out = (float*)d_out;

    float *pqkv, *py, *pxa, *pya, *pwqkvT, *pwoT;
    cudaGetSymbolAddress((void**)&pqkv, g_qkv);
    cudaGetSymbolAddress((void**)&py, g_y);
    cudaGetSymbolAddress((void**)&pxa, g_xa);
    cudaGetSymbolAddress((void**)&pya, g_ya);
    cudaGetSymbolAddress((void**)&pwqkvT, g_wqkvT);
    cudaGetSymbolAddress((void**)&pwoT, g_woT);

    // fragment-major packing (tf32 rounding folded in)
    pack_a<<<dim3(64, 32), 256>>>(x, pxa);
    pack_b<<<dim3(64, 8), 256>>>(Wq, pwqkvT, 1024, 0);
    pack_b<<<dim3(64, 2), 256>>>(Wk, pwqkvT, 256, 8);
    pack_b<<<dim3(64, 2), 256>>>(Wv, pwqkvT, 256, 10);
    pack_b<<<dim3(64, 8), 256>>>(Wo, pwoT, 1024, 0);

    cudaFuncSetAttribute(gemm_fm, cudaFuncAttributeMaxDynamicSharedMemorySize, GFM_SMEM);

    // fused QKV projection
    gemm_fm<<<dim3(12, 32), 256, GFM_SMEM>>>(pxa, pwqkvT, pqkv, 64, QKVLD);

    // fused v-gate + RoPE/RMSNorm + bf16 hi/lo packing
    prep_kernel<<<BB * SS * (NH + 2 * NKV), HD>>>(cosp, sinp, x, ve, Wg);

    // flash attention
    {
        int smem = (4 * TILEF + 128 * ATS + 256) * sizeof(float);   // 105472 B
        cudaFuncSetAttribute(attn_tc, cudaFuncAttributeMaxDynamicSharedMemorySize, smem);
        attn_tc<<<BB * NH * (SS / 128), 256, smem>>>(win);
    }

    // repack attention output for the Wo GEMM, then output projection
    pack_a<<<dim3(64, 32), 256>>>(py, pya);
    gemm_fm<<<dim3(8, 32), 256, GFM_SMEM>>>(pya, pwoT, out, 64, DD);
}

// round 11
// speedup vs baseline: 1.0742x; 1.0742x over previous
#include <cuda_runtime.h>
#include <cuda_bf16.h>
#include <math.h>
#include <stdint.h>

#define BB 2
#define SS 2048
#define DD 1024
#define NH 16
#define NKV 4
#define HD 64
#define GATE_CH 12
#define EPSV 1e-6f
#define QKVLD 1536   // qkv buffer row stride: [q(1024) | k(256) | v(256)]

// ---------------- device scratch (allocation-free rule) ----------------
__device__ float    g_qkv[BB * SS * QKVLD];     // fp32 qkv (row-major)
__device__ float    g_y[BB * SS * DD];          // attention output (row-major)
__device__ float    g_xa[(size_t)32 * 64 * 2048];    // x, fragment-major A tiles
__device__ float    g_ya[(size_t)32 * 64 * 2048];    // y, fragment-major A tiles
__device__ float    g_wqkvT[(size_t)12 * 64 * 2048]; // Wq|Wk|Wv, fragment-major B tiles
__device__ float    g_woT[(size_t)8 * 64 * 2048];    // Wo, fragment-major B tiles
__device__ uint32_t g_qpk[BB * SS * NH * 64];   // q packed bf16 hi|lo
__device__ uint32_t g_kpk[BB * SS * NKV * 64];  // k packed bf16 hi|lo

// ---------------- helpers ----------------
__device__ __forceinline__ float to_tf32(float x) {
    float r; asm("cvt.rna.tf32.f32 %0, %1;" : "=f"(r) : "f"(x)); return r;
}
__device__ __forceinline__ uint32_t pack_bf16(float e, float o) {
    uint16_t a = __bfloat16_as_ushort(__float2bfloat16(e));
    uint16_t b = __bfloat16_as_ushort(__float2bfloat16(o));
    return ((uint32_t)b << 16) | a;
}
__device__ __forceinline__ void mma_tf32(float* d, const uint32_t* a, const uint32_t* b) {
    asm volatile(
        "mma.sync.aligned.m16n8k8.row.col.f32.tf32.tf32.f32 "
        "{%0,%1,%2,%3}, {%4,%5,%6,%7}, {%8,%9}, {%0,%1,%2,%3};\n"
        : "+f"(d[0]), "+f"(d[1]), "+f"(d[2]), "+f"(d[3])
        : "r"(a[0]), "r"(a[1]), "r"(a[2]), "r"(a[3]), "r"(b[0]), "r"(b[1]));
}
__device__ __forceinline__ void mma_bf16(float* d, const uint32_t* a, const uint32_t* b) {
    asm volatile(
        "mma.sync.aligned.m16n8k16.row.col.f32.bf16.bf16.f32 "
        "{%0,%1,%2,%3}, {%4,%5,%6,%7}, {%8,%9}, {%0,%1,%2,%3};\n"
        : "+f"(d[0]), "+f"(d[1]), "+f"(d[2]), "+f"(d[3])
        : "r"(a[0]), "r"(a[1]), "r"(a[2]), "r"(a[3]), "r"(b[0]), "r"(b[1]));
}
__device__ __forceinline__ void cp_async16(uint32_t saddr, const void* gptr) {
    asm volatile("cp.async.cg.shared.global [%0], [%1], 16;" :: "r"(saddr), "l"(gptr));
}
#define CP_COMMIT() asm volatile("cp.async.commit_group;")
#define CP_WAIT(n)  asm volatile("cp.async.wait_group %0;" :: "n"(n))

// ---------------------------------------------------------------------------
// pack_a: row-major [M][1024] fp32 -> fragment-major A tiles (tf32-rounded).
// ---------------------------------------------------------------------------
__global__ void pack_a(const float* __restrict__ src, float* __restrict__ dst)
{
    int kt = blockIdx.x, rt = blockIdx.y;
    float* dtile = dst + ((size_t)rt * 64 + kt) * 2048;
    const float* s = src + (size_t)rt * 128 * 1024 + kt * 16;
    for (int q = threadIdx.x; q < 512; q += 256) {
        int gb = q >> 5;
        int g = gb >> 3, b = gb & 7;
        int lane = q & 31;
        int gid = lane >> 2, tig = lane & 3;
        const float* p = s + (size_t)(b * 16 + gid) * 1024 + g * 8 + tig;
        float4 v;
        v.x = to_tf32(p[0]);
        v.y = to_tf32(p[8 * 1024]);
        v.z = to_tf32(p[4]);
        v.w = to_tf32(p[8 * 1024 + 4]);
        *(float4*)(dtile + q * 4) = v;
    }
}

// ---------------------------------------------------------------------------
// pack_b: W[K][n_src] row-major -> fragment-major B tiles at col-tile ct0+cl.
// ---------------------------------------------------------------------------
__global__ void pack_b(const float* __restrict__ W, float* __restrict__ dst,
                       int n_src, int ct0)
{
    int kt = blockIdx.x, cl = blockIdx.y;
    float* dtile = dst + ((size_t)(ct0 + cl) * 64 + kt) * 2048;
    const float* s = W + (size_t)kt * 16 * n_src + cl * 128;
    for (int q = threadIdx.x; q < 512; q += 256) {
        int plane = q >> 8;
        int q8 = q & 255;
        int gw = q8 >> 5;
        int g = gw >> 2, w = gw & 3;
        int lane = q8 & 31;
        int gid = lane >> 2, tig = lane & 3;
        const float* p = s + (size_t)(g * 8 + tig + plane * 4) * n_src + w * 32 + gid;
        float4 v;
        v.x = to_tf32(p[0]);
        v.y = to_tf32(p[8]);
        v.z = to_tf32(p[16]);
        v.w = to_tf32(p[24]);
        *(float4*)(dtile + q * 4) = v;
    }
}

// ---------------------------------------------------------------------------
// gemm_fm: tf32 HMMA GEMM on fragment-major tiles, BK=32 (2 k-tiles/stage),
// 3-stage cp.async. CTA 128x128, 256 thr, warp tile 64x32.
// stage = 32KB: [A t0 8K][A t1 8K][B t0 8K][B t1 8K]; dyn smem 98304 B.
// Accumulation order identical to BK=16 version (tiles consumed in sequence).
// ---------------------------------------------------------------------------
#define GFM_SMEM 98304
__global__ __launch_bounds__(256, 2) void gemm_fm(
    const float* __restrict__ At, const float* __restrict__ Bt,
    float* __restrict__ C, int nkt, int ldc)
{
    extern __shared__ float smg[];
    uint32_t smb = (uint32_t)__cvta_generic_to_shared(smg);
    const int tid = threadIdx.x;
    const int lane = tid & 31, wid = tid >> 5;
    const int gid = lane >> 2, tig = lane & 3;
    const int wm4 = (wid >> 2) * 4;     // warp_m / 16
    const int wn5 = wid & 3;            // warp_n / 32
    const int rowBase = blockIdx.y * 128, colBase = blockIdx.x * 128;

    const float* Abase = At + (size_t)blockIdx.y * nkt * 2048 + tid * 8;
    const float* Bbase = Bt + (size_t)blockIdx.x * nkt * 2048 + tid * 8;

    // stage pair p (k-tiles 2p, 2p+1) into slot s
#define FM_STAGE(p, s) do { \
    uint32_t _d = smb + (s) * 32768 + tid * 32; \
    const float* _a = Abase + (size_t)(p) * 4096; \
    const float* _b = Bbase + (size_t)(p) * 4096; \
    cp_async16(_d,            _a);        cp_async16(_d + 16,           _a + 4); \
    cp_async16(_d + 8192,     _a + 2048); cp_async16(_d + 8192 + 16,    _a + 2052); \
    cp_async16(_d + 16384,    _b);        cp_async16(_d + 16384 + 16,   _b + 4); \
    cp_async16(_d + 24576,    _b + 2048); cp_async16(_d + 24576 + 16,   _b + 2052); \
    CP_COMMIT(); \
} while (0)

    FM_STAGE(0, 0);
    FM_STAGE(1, 1);

    float acc[4][4][4] = {};
    const int np = nkt >> 1;   // pairs
    for (int it = 0; it < np; it++) {
        const int s = it % 3;
        __syncthreads();                       // compute(it-1) done before restage
        if (it + 2 < np) {
            FM_STAGE(it + 2, (it + 2) % 3);
            CP_WAIT(2);
        } else if (it + 1 < np) {
            CP_WAIT(1);
        } else {
            CP_WAIT(0);
        }
        __syncthreads();                       // staged data visible

#pragma unroll
        for (int t01 = 0; t01 < 2; t01++) {
            const uint4* As4 = (const uint4*)(smg + s * 8192 + t01 * 2048);
            const uint4* Bs4 = (const uint4*)(smg + s * 8192 + 4096 + t01 * 2048);
#pragma unroll
            for (int g = 0; g < 2; g++) {
                uint4 afr[4];
#pragma unroll
                for (int mi = 0; mi < 4; mi++)
                    afr[mi] = As4[(g * 8 + wm4 + mi) * 32 + lane];
                uint4 b0 = Bs4[(g * 4 + wn5) * 32 + lane];
                uint4 b1 = Bs4[256 + (g * 4 + wn5) * 32 + lane];
                uint32_t bf[4][2] = {
                    {b0.x, b1.x}, {b0.y, b1.y}, {b0.z, b1.z}, {b0.w, b1.w}};
#pragma unroll
                for (int mi = 0; mi < 4; mi++) {
                    const uint32_t* af = (const uint32_t*)&afr[mi];
#pragma unroll
                    for (int ni = 0; ni < 4; ni++)
                        mma_tf32(acc[mi][ni], af, bf[ni]);
                }
            }
        }
    }

    const int warp_m = wm4 * 16, warp_n = wn5 * 32;
#pragma unroll
    for (int mi = 0; mi < 4; mi++) {
#pragma unroll
        for (int ni = 0; ni < 4; ni++) {
            int row = rowBase + warp_m + mi * 16 + gid;
            int col = colBase + warp_n + ni * 8 + 2 * tig;
            *(float2*)(C + (size_t)row * ldc + col) =
                make_float2(acc[mi][ni][0], acc[mi][ni][1]);
            *(float2*)(C + (size_t)(row + 8) * ldc + col) =
                make_float2(acc[mi][ni][2], acc[mi][ni][3]);
        }
    }
}

// ---------------------------------------------------------------------------
// Fused prep, 256-thread blocks (4 head-units per block).
// blk%6 in [0,5): rope units (hh 0..19); blk%6==5: vgate units (hh 20..23).
// grid = B*S*6, block 256
// ---------------------------------------------------------------------------
__global__ void prep_kernel(const float* __restrict__ cosp,
                            const float* __restrict__ sinp,
                            const float* __restrict__ x,
                            const float* __restrict__ ve,
                            const float* __restrict__ Wg)
{
    int blk = blockIdx.x;
    int grp = blk % 6;
    int bs = blk / 6;
    int unit = threadIdx.x >> 6;        // 0..3
    int d = threadIdx.x & 63;
    int hh = grp * 4 + unit;

    if (hh >= NH + NKV) {
        // ---- v gate (whole block takes this branch: grp==5) ----
        int kvh = hh - (NH + NKV);
        const float* xr = x + (size_t)bs * DD;
        float g = 0.f;
#pragma unroll
        for (int c = 0; c < GATE_CH; c++) g += xr[c] * Wg[c * NKV + kvh];
        g = 3.f / (1.f + __expf(-g));
        float* vp = &g_qkv[(size_t)bs * QKVLD + 1280 + kvh * HD + d];
        *vp = to_tf32(*vp + g * ve[(size_t)bs * (NKV * HD) + kvh * HD + d]);
        return;
    }

    // ---- RoPE + RMSNorm ----
    int s = bs % SS;
    const float* ptr = g_qkv + (size_t)bs * QKVLD +
                       ((hh < NH) ? hh * HD : 1024 + (hh - NH) * HD);

    int half = d & 31;
    float c  = cosp[s * 32 + half];
    float sn = sinp[s * 32 + half];
    float x1 = ptr[half];
    float x2 = ptr[half + 32];
    float rot = (d < 32) ? (x1 * c + x2 * sn) : (-x1 * sn + x2 * c);

    __shared__ float red[4][2];
    float v = rot * rot;
#pragma unroll
    for (int o = 16; o > 0; o >>= 1) v += __shfl_xor_sync(0xffffffffu, v, o);
    if ((d & 31) == 0) red[unit][d >> 5] = v;
    __syncthreads();
    float total = red[unit][0] + red[unit][1];
    float r = rsqrtf(total * (1.f / HD) + EPSV) * 1.2f;
    float val = rot * r;
    if (hh < NH) val *= 0.125f;

    float hif = __bfloat162float(__float2bfloat16(val));
    float lof = val - hif;
    float val_o = __shfl_down_sync(0xffffffffu, val, 1);
    float lof_o = __shfl_down_sync(0xffffffffu, lof, 1);

    if ((d & 1) == 0) {
        uint32_t hp = pack_bf16(val, val_o);
        uint32_t lp = pack_bf16(lof, lof_o);
        uint32_t* out = (hh < NH)
            ? &g_qpk[((size_t)bs * NH + hh) * 64]
            : &g_kpk[((size_t)bs * NKV + (hh - NH)) * 64];
        out[d >> 1]        = hp;
        out[32 + (d >> 1)] = lp;
    }
}

// ---------------------------------------------------------------------------
// Tensor-core flash attention, 128 queries/CTA, 8 warps (unchanged from R10).
// ---------------------------------------------------------------------------
#define ATS 68
#define TILEF (64 * ATS)
__global__ __launch_bounds__(256, 2) void attn_tc(const int* __restrict__ winp)
{
    const int win = *winp;
    int bid = blockIdx.x;
    int qt = bid & 15;
    int bh = bid >> 4;
    int h = bh % NH;
    int b = bh / NH;
    int q0 = qt * 128;
    int kvh = h / (NH / NKV);

    const int tid = threadIdx.x;
    const int lane = tid & 31;
    const int warp = tid >> 5;
    const int wrow = warp * 16;
    const int gid = lane >> 2;
    const int tig = lane & 3;

    extern __shared__ float sm[];
    uint32_t* Khl0 = (uint32_t*)sm;
    float* Ss   = sm + 4 * TILEF;
    float* scb  = sm + 4 * TILEF + 128 * ATS;
    float* lbuf = scb + 128;
    uint32_t smbase = (uint32_t)__cvta_generic_to_shared(sm);

    const int st_r  = tid >> 4;
    const int st_c4 = (tid & 15) * 4;

    {
        uint32_t* Qs = (uint32_t*)Ss;
        for (int i = tid; i < 128 * 16; i += 256) {
            int r = i >> 4;
            int c4 = (i & 15) * 4;
            *(uint4*)&Qs[r * ATS + c4] =
                *(const uint4*)(g_qpk + ((size_t)(b * SS + q0 + r) * NH + h) * 64 + c4);
        }
    }
    __syncthreads();

    uint32_t ahi[4][4], alo[4][4];
    {
        const uint32_t* Qs = (const uint32_t*)Ss;
#pragma unroll
        for (int ks = 0; ks < 4; ks++) {
            int cb = ks * 8 + tig;
            ahi[ks][0] = Qs[(wrow + gid) * ATS + cb];
            ahi[ks][1] = Qs[(wrow + gid + 8) * ATS + cb];
            ahi[ks][2] = Qs[(wrow + gid) * ATS + cb + 4];
            ahi[ks][3] = Qs[(wrow + gid + 8) * ATS + cb + 4];
            alo[ks][0] = Qs[(wrow + gid) * ATS + 32 + cb];
            alo[ks][1] = Qs[(wrow + gid + 8) * ATS + 32 + cb];
            alo[ks][2] = Qs[(wrow + gid) * ATS + 32 + cb + 4];
            alo[ks][3] = Qs[(wrow + gid + 8) * ATS + 32 + cb + 4];
        }
    }

    float m = -1e30f, lsum = 0.f;
    float oacc[8][4] = {};

    int kmin = q0 - win + 1;
    if (kmin < 0) kmin = 0;
    int t0 = kmin >> 6;
    int t1 = (q0 + 127) >> 6;

    {
        int kb = t0 << 6;
        const uint32_t* ksrc = g_kpk + ((size_t)(b * SS + kb + st_r) * NKV + kvh) * 64 + st_c4;
        const float* vsrc = g_qkv + (size_t)(b * SS + kb + st_r) * QKVLD + 1280 + kvh * HD + st_c4;
        uint32_t kdst = smbase + (0 * TILEF + st_r * ATS + st_c4) * 4;
        uint32_t vdst = smbase + (2 * TILEF + st_r * ATS + st_c4) * 4;
#pragma unroll
        for (int j = 0; j < 4; j++) {
            cp_async16(kdst + j * 16 * ATS * 4, ksrc + (size_t)j * 16 * NKV * 64);
            cp_async16(vdst + j * 16 * ATS * 4, vsrc + (size_t)j * 16 * QKVLD);
        }
        CP_COMMIT();
    }

    for (int t = t0; t <= t1; t++) {
        int kb = t << 6;
        const int buf = (t - t0) & 1;
        __syncthreads();
        if (t < t1) {
            int nb = (t + 1) << 6;
            const uint32_t* ksrc = g_kpk + ((size_t)(b * SS + nb + st_r) * NKV + kvh) * 64 + st_c4;
            const float* vsrc = g_qkv + (size_t)(b * SS + nb + st_r) * QKVLD + 1280 + kvh * HD + st_c4;
            uint32_t kdst = smbase + ((buf ^ 1) * TILEF + st_r * ATS + st_c4) * 4;
            uint32_t vdst = smbase + ((2 + (buf ^ 1)) * TILEF + st_r * ATS + st_c4) * 4;
#pragma unroll
            for (int j = 0; j < 4; j++) {
                cp_async16(kdst + j * 16 * ATS * 4, ksrc + (size_t)j * 16 * NKV * 64);
                cp_async16(vdst + j * 16 * ATS * 4, vsrc + (size_t)j * 16 * QKVLD);
            }
            CP_COMMIT();
            CP_WAIT(1);
        } else {
            CP_WAIT(0);
        }
        __syncthreads();

        bool active = (kb <= q0 + wrow + 15) && (kb + 63 >= q0 + wrow - win + 1);
        if (active) {
            const uint32_t* Khl = Khl0 + buf * TILEF;
            const float* Vs = sm + (2 + buf) * TILEF;

            float accS[8][4] = {};
#pragma unroll
            for (int ks = 0; ks < 4; ks++) {
#pragma unroll
                for (int ni = 0; ni < 8; ni++) {
                    const uint32_t* kr = &Khl[(ni * 8 + gid) * ATS + ks * 8 + tig];
                    uint32_t bh2[2] = { kr[0],  kr[4] };
                    uint32_t bl2[2] = { kr[32], kr[36] };
                    mma_bf16(accS[ni], ahi[ks], bh2);
                    mma_bf16(accS[ni], alo[ks], bh2);
                    mma_bf16(accS[ni], ahi[ks], bl2);
                }
            }

#pragma unroll
            for (int ni = 0; ni < 8; ni++) {
#pragma unroll
                for (int j = 0; j < 4; j++) {
                    int col = ni * 8 + 2 * tig + (j & 1);
                    int r = gid + ((j >> 1) << 3);
                    int qpos = q0 + wrow + r;
                    int kpos = kb + col;
                    bool ok = (kpos <= qpos) && (kpos >= qpos - win + 1);
                    Ss[(wrow + r) * ATS + col] = ok ? accS[ni][j] : -1e30f;
                }
            }
            __syncwarp();

            {
                int srow = lane >> 1;
                int cb = (lane & 1) * 32;
                float* sp = &Ss[(wrow + srow) * ATS + cb];
                float rmax = -1e30f;
#pragma unroll
                for (int c = 0; c < 32; c++) rmax = fmaxf(rmax, sp[c]);
                rmax = fmaxf(rmax, __shfl_xor_sync(0xffffffffu, rmax, 1));
                float mnew = fmaxf(m, rmax);
                float scale, rs = 0.f;
                if (mnew <= -1e20f) {
                    scale = 1.f;
#pragma unroll
                    for (int c = 0; c < 32; c++) sp[c] = 0.f;
                } else {
                    scale = __expf(m - mnew);
#pragma unroll
                    for (int c = 0; c < 32; c++) {
                        float p = __expf(sp[c] - mnew);
                        rs += p;
                        sp[c] = to_tf32(p);
                    }
                }
                m = mnew;
                rs += __shfl_xor_sync(0xffffffffu, rs, 1);
                lsum = lsum * scale + rs;
                if ((lane & 1) == 0) scb[wrow + srow] = scale;
            }
            __syncwarp();

            {
                float sc0 = scb[wrow + gid];
                float sc1 = scb[wrow + gid + 8];
#pragma unroll
                for (int ni = 0; ni < 8; ni++) {
                    oacc[ni][0] *= sc0; oacc[ni][1] *= sc0;
                    oacc[ni][2] *= sc1; oacc[ni][3] *= sc1;
                }
            }
#pragma unroll
            for (int ks = 0; ks < 8; ks++) {
                uint32_t pa[4];
                pa[0] = __float_as_uint(Ss[(wrow + gid) * ATS + ks * 8 + tig]);
                pa[1] = __float_as_uint(Ss[(wrow + gid + 8) * ATS + ks * 8 + tig]);
                pa[2] = __float_as_uint(Ss[(wrow + gid) * ATS + ks * 8 + tig + 4]);
                pa[3] = __float_as_uint(Ss[(wrow + gid + 8) * ATS + ks * 8 + tig + 4]);
#pragma unroll
                for (int ni = 0; ni < 8; ni++) {
                    uint32_t vb[2];
                    vb[0] = __float_as_uint(Vs[(ks * 8 + tig) * ATS + ni * 8 + gid]);
                    vb[1] = __float_as_uint(Vs[(ks * 8 + tig + 4) * ATS + ni * 8 + gid]);
                    mma_tf32(oacc[ni], pa, vb);
                }
            }
        }
    }

    if ((lane & 1) == 0) lbuf[wrow + (lane >> 1)] = lsum;
    __syncwarp();
    float li0 = 1.f / lbuf[wrow + gid];
    float li1 = 1.f / lbuf[wrow + gid + 8];

#pragma unroll
    for (int ni = 0; ni < 8; ni++) {
        int col = h * HD + ni * 8 + 2 * tig;
        int row0 = b * SS + q0 + wrow + gid;
        *(float2*)(g_y + (size_t)row0 * DD + col) =
            make_float2(to_tf32(oacc[ni][0] * li0), to_tf32(oacc[ni][1] * li0));
        *(float2*)(g_y + (size_t)(row0 + 8) * DD + col) =
            make_float2(to_tf32(oacc[ni][2] * li1), to_tf32(oacc[ni][3] * li1));
    }
}

// ---------------------------------------------------------------------------
extern "C" void kernel_launch(void* const* d_in, const int* in_sizes, int n_in,
                              void* d_out, int out_size)
{
    const float* x    = (const float*)d_in[0];
    const float* ve   = (const float*)d_in[1];
    const float* cosp = (const float*)d_in[2];
    const float* sinp = (const float*)d_in[3];
    const float* Wq   = (const float*)d_in[4];
    const float* Wk   = (const float*)d_in[5];
    const float* Wv   = (const float*)d_in[6];
    const float* Wo   = (const float*)d_in[7];
    const float* Wg   = (const float*)d_in[8];
    const int*   win  = (const int*)d_in[9];
    float* out = (float*)d_out;

    float *pqkv, *py, *pxa, *pya, *pwqkvT, *pwoT;
    cudaGetSymbolAddress((void**)&pqkv, g_qkv);
    cudaGetSymbolAddress((void**)&py, g_y);
    cudaGetSymbolAddress((void**)&pxa, g_xa);
    cudaGetSymbolAddress((void**)&pya, g_ya);
    cudaGetSymbolAddress((void**)&pwqkvT, g_wqkvT);
    cudaGetSymbolAddress((void**)&pwoT, g_woT);

    // fragment-major packing (tf32 rounding folded in)
    pack_a<<<dim3(64, 32), 256>>>(x, pxa);
    pack_b<<<dim3(64, 8), 256>>>(Wq, pwqkvT, 1024, 0);
    pack_b<<<dim3(64, 2), 256>>>(Wk, pwqkvT, 256, 8);
    pack_b<<<dim3(64, 2), 256>>>(Wv, pwqkvT, 256, 10);
    pack_b<<<dim3(64, 8), 256>>>(Wo, pwoT, 1024, 0);

    cudaFuncSetAttribute(gemm_fm, cudaFuncAttributeMaxDynamicSharedMemorySize, GFM_SMEM);

    // fused QKV projection (BK=32, halved barrier count)
    gemm_fm<<<dim3(12, 32), 256, GFM_SMEM>>>(pxa, pwqkvT, pqkv, 64, QKVLD);

    // fused v-gate + RoPE/RMSNorm + bf16 hi/lo packing (256-thr blocks)
    prep_kernel<<<BB * SS * 6, 256>>>(cosp, sinp, x, ve, Wg);

    // flash attention
    {
        int smem = (4 * TILEF + 128 * ATS + 256) * sizeof(float);   // 105472 B
        cudaFuncSetAttribute(attn_tc, cudaFuncAttributeMaxDynamicSharedMemorySize, smem);
        attn_tc<<<BB * NH * (SS / 128), 256, smem>>>(win);
    }

    // repack attention output for the Wo GEMM, then output projection
    pack_a<<<dim3(64, 32), 256>>>(py, pya);
    gemm_fm<<<dim3(8, 32), 256, GFM_SMEM>>>(pya, pwoT, out, 64, DD);
}

// round 12
// speedup vs baseline: 1.0797x; 1.0050x over previous
#include <cuda_runtime.h>
#include <cuda_bf16.h>
#include <math.h>
#include <stdint.h>

#define BB 2
#define SS 2048
#define DD 1024
#define NH 16
#define NKV 4
#define HD 64
#define GATE_CH 12
#define EPSV 1e-6f
#define QKVLD 1536   // qkv buffer row stride: [q(1024) | k(256) | v(256)]

// ---------------- device scratch (allocation-free rule) ----------------
__device__ float    g_qkv[BB * SS * QKVLD];     // fp32 qkv (row-major)
__device__ float    g_xa[(size_t)32 * 64 * 2048];    // x, fragment-major A tiles
__device__ float    g_ya[(size_t)32 * 64 * 2048];    // attn out, fragment-major A tiles
__device__ float    g_wqkvT[(size_t)12 * 64 * 2048]; // Wq|Wk|Wv, fragment-major B tiles
__device__ float    g_woT[(size_t)8 * 64 * 2048];    // Wo, fragment-major B tiles
__device__ uint32_t g_qpk[BB * SS * NH * 64];   // q packed bf16 hi|lo
__device__ uint32_t g_kpk[BB * SS * NKV * 64];  // k packed bf16 hi|lo

// ---------------- helpers ----------------
__device__ __forceinline__ float to_tf32(float x) {
    float r; asm("cvt.rna.tf32.f32 %0, %1;" : "=f"(r) : "f"(x)); return r;
}
__device__ __forceinline__ uint32_t pack_bf16(float e, float o) {
    uint16_t a = __bfloat16_as_ushort(__float2bfloat16(e));
    uint16_t b = __bfloat16_as_ushort(__float2bfloat16(o));
    return ((uint32_t)b << 16) | a;
}
__device__ __forceinline__ void mma_tf32(float* d, const uint32_t* a, const uint32_t* b) {
    asm volatile(
        "mma.sync.aligned.m16n8k8.row.col.f32.tf32.tf32.f32 "
        "{%0,%1,%2,%3}, {%4,%5,%6,%7}, {%8,%9}, {%0,%1,%2,%3};\n"
        : "+f"(d[0]), "+f"(d[1]), "+f"(d[2]), "+f"(d[3])
        : "r"(a[0]), "r"(a[1]), "r"(a[2]), "r"(a[3]), "r"(b[0]), "r"(b[1]));
}
__device__ __forceinline__ void mma_bf16(float* d, const uint32_t* a, const uint32_t* b) {
    asm volatile(
        "mma.sync.aligned.m16n8k16.row.col.f32.bf16.bf16.f32 "
        "{%0,%1,%2,%3}, {%4,%5,%6,%7}, {%8,%9}, {%0,%1,%2,%3};\n"
        : "+f"(d[0]), "+f"(d[1]), "+f"(d[2]), "+f"(d[3])
        : "r"(a[0]), "r"(a[1]), "r"(a[2]), "r"(a[3]), "r"(b[0]), "r"(b[1]));
}
__device__ __forceinline__ void cp_async16(uint32_t saddr, const void* gptr) {
    asm volatile("cp.async.cg.shared.global [%0], [%1], 16;" :: "r"(saddr), "l"(gptr));
}
#define CP_COMMIT() asm volatile("cp.async.commit_group;")
#define CP_WAIT(n)  asm volatile("cp.async.wait_group %0;" :: "n"(n))

// ---------------------------------------------------------------------------
// pack_a: row-major [M][1024] fp32 -> fragment-major A tiles (tf32-rounded).
// ---------------------------------------------------------------------------
__global__ void pack_a(const float* __restrict__ src, float* __restrict__ dst)
{
    int kt = blockIdx.x, rt = blockIdx.y;
    float* dtile = dst + ((size_t)rt * 64 + kt) * 2048;
    const float* s = src + (size_t)rt * 128 * 1024 + kt * 16;
    for (int q = threadIdx.x; q < 512; q += 256) {
        int gb = q >> 5;
        int g = gb >> 3, b = gb & 7;
        int lane = q & 31;
        int gid = lane >> 2, tig = lane & 3;
        const float* p = s + (size_t)(b * 16 + gid) * 1024 + g * 8 + tig;
        float4 v;
        v.x = to_tf32(p[0]);
        v.y = to_tf32(p[8 * 1024]);
        v.z = to_tf32(p[4]);
        v.w = to_tf32(p[8 * 1024 + 4]);
        *(float4*)(dtile + q * 4) = v;
    }
}

// ---------------------------------------------------------------------------
// pack_b: W[K][n_src] row-major -> fragment-major B tiles at col-tile ct0+cl.
// ---------------------------------------------------------------------------
__global__ void pack_b(const float* __restrict__ W, float* __restrict__ dst,
                       int n_src, int ct0)
{
    int kt = blockIdx.x, cl = blockIdx.y;
    float* dtile = dst + ((size_t)(ct0 + cl) * 64 + kt) * 2048;
    const float* s = W + (size_t)kt * 16 * n_src + cl * 128;
    for (int q = threadIdx.x; q < 512; q += 256) {
        int plane = q >> 8;
        int q8 = q & 255;
        int gw = q8 >> 5;
        int g = gw >> 2, w = gw & 3;
        int lane = q8 & 31;
        int gid = lane >> 2, tig = lane & 3;
        const float* p = s + (size_t)(g * 8 + tig + plane * 4) * n_src + w * 32 + gid;
        float4 v;
        v.x = to_tf32(p[0]);
        v.y = to_tf32(p[8]);
        v.z = to_tf32(p[16]);
        v.w = to_tf32(p[24]);
        *(float4*)(dtile + q * 4) = v;
    }
}

// ---------------------------------------------------------------------------
// gemm_fm: tf32 HMMA GEMM on fragment-major tiles, BK=32, 3-stage cp.async,
// SINGLE __syncthreads per mainloop iteration.
// CTA 128x128, 256 thr, warp tile 64x32. dyn smem 98304 B.
// ---------------------------------------------------------------------------
#define GFM_SMEM 98304
__global__ __launch_bounds__(256, 2) void gemm_fm(
    const float* __restrict__ At, const float* __restrict__ Bt,
    float* __restrict__ C, int nkt, int ldc)
{
    extern __shared__ float smg[];
    uint32_t smb = (uint32_t)__cvta_generic_to_shared(smg);
    const int tid = threadIdx.x;
    const int lane = tid & 31, wid = tid >> 5;
    const int gid = lane >> 2, tig = lane & 3;
    const int wm4 = (wid >> 2) * 4;
    const int wn5 = wid & 3;
    const int rowBase = blockIdx.y * 128, colBase = blockIdx.x * 128;

    const float* Abase = At + (size_t)blockIdx.y * nkt * 2048 + tid * 8;
    const float* Bbase = Bt + (size_t)blockIdx.x * nkt * 2048 + tid * 8;

#define FM_STAGE(p, s) do { \
    uint32_t _d = smb + (s) * 32768 + tid * 32; \
    const float* _a = Abase + (size_t)(p) * 4096; \
    const float* _b = Bbase + (size_t)(p) * 4096; \
    cp_async16(_d,            _a);        cp_async16(_d + 16,           _a + 4); \
    cp_async16(_d + 8192,     _a + 2048); cp_async16(_d + 8192 + 16,    _a + 2052); \
    cp_async16(_d + 16384,    _b);        cp_async16(_d + 16384 + 16,   _b + 4); \
    cp_async16(_d + 24576,    _b + 2048); cp_async16(_d + 24576 + 16,   _b + 2052); \
    CP_COMMIT(); \
} while (0)

    FM_STAGE(0, 0);
    FM_STAGE(1, 1);

    float acc[4][4][4] = {};
    const int np = nkt >> 1;
    for (int it = 0; it < np; it++) {
        const int s = it % 3;
        if (it + 1 < np) { CP_WAIT(1); } else { CP_WAIT(0); }
        __syncthreads();   // data(it) visible AND everyone done compute(it-1)
        if (it + 2 < np) FM_STAGE(it + 2, (it + 2) % 3);   // slot consumed at it-1

#pragma unroll
        for (int t01 = 0; t01 < 2; t01++) {
            const uint4* As4 = (const uint4*)(smg + s * 8192 + t01 * 2048);
            const uint4* Bs4 = (const uint4*)(smg + s * 8192 + 4096 + t01 * 2048);
#pragma unroll
            for (int g = 0; g < 2; g++) {
                uint4 afr[4];
#pragma unroll
                for (int mi = 0; mi < 4; mi++)
                    afr[mi] = As4[(g * 8 + wm4 + mi) * 32 + lane];
                uint4 b0 = Bs4[(g * 4 + wn5) * 32 + lane];
                uint4 b1 = Bs4[256 + (g * 4 + wn5) * 32 + lane];
                uint32_t bf[4][2] = {
                    {b0.x, b1.x}, {b0.y, b1.y}, {b0.z, b1.z}, {b0.w, b1.w}};
#pragma unroll
                for (int mi = 0; mi < 4; mi++) {
                    const uint32_t* af = (const uint32_t*)&afr[mi];
#pragma unroll
                    for (int ni = 0; ni < 4; ni++)
                        mma_tf32(acc[mi][ni], af, bf[ni]);
                }
            }
        }
    }

    const int warp_m = wm4 * 16, warp_n = wn5 * 32;
#pragma unroll
    for (int mi = 0; mi < 4; mi++) {
#pragma unroll
        for (int ni = 0; ni < 4; ni++) {
            int row = rowBase + warp_m + mi * 16 + gid;
            int col = colBase + warp_n + ni * 8 + 2 * tig;
            *(float2*)(C + (size_t)row * ldc + col) =
                make_float2(acc[mi][ni][0], acc[mi][ni][1]);
            *(float2*)(C + (size_t)(row + 8) * ldc + col) =
                make_float2(acc[mi][ni][2], acc[mi][ni][3]);
        }
    }
}

// ---------------------------------------------------------------------------
// Fused prep, 256-thread blocks (4 head-units per block).
// ---------------------------------------------------------------------------
__global__ void prep_kernel(const float* __restrict__ cosp,
                            const float* __restrict__ sinp,
                            const float* __restrict__ x,
                            const float* __restrict__ ve,
                            const float* __restrict__ Wg)
{
    int blk = blockIdx.x;
    int grp = blk % 6;
    int bs = blk / 6;
    int unit = threadIdx.x >> 6;
    int d = threadIdx.x & 63;
    int hh = grp * 4 + unit;

    if (hh >= NH + NKV) {
        int kvh = hh - (NH + NKV);
        const float* xr = x + (size_t)bs * DD;
        float g = 0.f;
#pragma unroll
        for (int c = 0; c < GATE_CH; c++) g += xr[c] * Wg[c * NKV + kvh];
        g = 3.f / (1.f + __expf(-g));
        float* vp = &g_qkv[(size_t)bs * QKVLD + 1280 + kvh * HD + d];
        *vp = to_tf32(*vp + g * ve[(size_t)bs * (NKV * HD) + kvh * HD + d]);
        return;
    }

    int s = bs % SS;
    const float* ptr = g_qkv + (size_t)bs * QKVLD +
                       ((hh < NH) ? hh * HD : 1024 + (hh - NH) * HD);

    int half = d & 31;
    float c  = cosp[s * 32 + half];
    float sn = sinp[s * 32 + half];
    float x1 = ptr[half];
    float x2 = ptr[half + 32];
    float rot = (d < 32) ? (x1 * c + x2 * sn) : (-x1 * sn + x2 * c);

    __shared__ float red[4][2];
    float v = rot * rot;
#pragma unroll
    for (int o = 16; o > 0; o >>= 1) v += __shfl_xor_sync(0xffffffffu, v, o);
    if ((d & 31) == 0) red[unit][d >> 5] = v;
    __syncthreads();
    float total = red[unit][0] + red[unit][1];
    float r = rsqrtf(total * (1.f / HD) + EPSV) * 1.2f;
    float val = rot * r;
    if (hh < NH) val *= 0.125f;

    float hif = __bfloat162float(__float2bfloat16(val));
    float lof = val - hif;
    float val_o = __shfl_down_sync(0xffffffffu, val, 1);
    float lof_o = __shfl_down_sync(0xffffffffu, lof, 1);

    if ((d & 1) == 0) {
        uint32_t hp = pack_bf16(val, val_o);
        uint32_t lp = pack_bf16(lof, lof_o);
        uint32_t* out = (hh < NH)
            ? &g_qpk[((size_t)bs * NH + hh) * 64]
            : &g_kpk[((size_t)bs * NKV + (hh - NH)) * 64];
        out[d >> 1]        = hp;
        out[32 + (d >> 1)] = lp;
    }
}

// ---------------------------------------------------------------------------
// Tensor-core flash attention, 128 queries/CTA, 8 warps.
// SINGLE __syncthreads per K/V tile. Epilogue writes fragment-major g_ya.
// ---------------------------------------------------------------------------
#define ATS 68
#define TILEF (64 * ATS)
__global__ __launch_bounds__(256, 2) void attn_tc(const int* __restrict__ winp)
{
    const int win = *winp;
    int bid = blockIdx.x;
    int qt = bid & 15;
    int bh = bid >> 4;
    int h = bh % NH;
    int b = bh / NH;
    int q0 = qt * 128;
    int kvh = h / (NH / NKV);

    const int tid = threadIdx.x;
    const int lane = tid & 31;
    const int warp = tid >> 5;
    const int wrow = warp * 16;
    const int gid = lane >> 2;
    const int tig = lane & 3;

    extern __shared__ float sm[];
    uint32_t* Khl0 = (uint32_t*)sm;
    float* Ss   = sm + 4 * TILEF;
    float* scb  = sm + 4 * TILEF + 128 * ATS;
    float* lbuf = scb + 128;
    uint32_t smbase = (uint32_t)__cvta_generic_to_shared(sm);

    const int st_r  = tid >> 4;
    const int st_c4 = (tid & 15) * 4;

    {
        uint32_t* Qs = (uint32_t*)Ss;
        for (int i = tid; i < 128 * 16; i += 256) {
            int r = i >> 4;
            int c4 = (i & 15) * 4;
            *(uint4*)&Qs[r * ATS + c4] =
                *(const uint4*)(g_qpk + ((size_t)(b * SS + q0 + r) * NH + h) * 64 + c4);
        }
    }
    __syncthreads();

    uint32_t ahi[4][4], alo[4][4];
    {
        const uint32_t* Qs = (const uint32_t*)Ss;
#pragma unroll
        for (int ks = 0; ks < 4; ks++) {
            int cb = ks * 8 + tig;
            ahi[ks][0] = Qs[(wrow + gid) * ATS + cb];
            ahi[ks][1] = Qs[(wrow + gid + 8) * ATS + cb];
            ahi[ks][2] = Qs[(wrow + gid) * ATS + cb + 4];
            ahi[ks][3] = Qs[(wrow + gid + 8) * ATS + cb + 4];
            alo[ks][0] = Qs[(wrow + gid) * ATS + 32 + cb];
            alo[ks][1] = Qs[(wrow + gid + 8) * ATS + 32 + cb];
            alo[ks][2] = Qs[(wrow + gid) * ATS + 32 + cb + 4];
            alo[ks][3] = Qs[(wrow + gid + 8) * ATS + 32 + cb + 4];
        }
    }

    float m = -1e30f, lsum = 0.f;
    float oacc[8][4] = {};

    int kmin = q0 - win + 1;
    if (kmin < 0) kmin = 0;
    int t0 = kmin >> 6;
    int t1 = (q0 + 127) >> 6;

#define AT_STAGE(tt, bf) do { \
    int _kb = (tt) << 6; \
    const uint32_t* _ks = g_kpk + ((size_t)(b * SS + _kb + st_r) * NKV + kvh) * 64 + st_c4; \
    const float* _vs = g_qkv + (size_t)(b * SS + _kb + st_r) * QKVLD + 1280 + kvh * HD + st_c4; \
    uint32_t _kd = smbase + ((bf) * TILEF + st_r * ATS + st_c4) * 4; \
    uint32_t _vd = smbase + ((2 + (bf)) * TILEF + st_r * ATS + st_c4) * 4; \
    _Pragma("unroll") \
    for (int _j = 0; _j < 4; _j++) { \
        cp_async16(_kd + _j * 16 * ATS * 4, _ks + (size_t)_j * 16 * NKV * 64); \
        cp_async16(_vd + _j * 16 * ATS * 4, _vs + (size_t)_j * 16 * QKVLD); \
    } \
    CP_COMMIT(); \
} while (0)

    AT_STAGE(t0, 0);

    for (int t = t0; t <= t1; t++) {
        int kb = t << 6;
        const int buf = (t - t0) & 1;
        CP_WAIT(0);
        __syncthreads();   // tile t visible; everyone done reading buf^1 (iter t-1)
        if (t < t1) AT_STAGE(t + 1, buf ^ 1);

        bool active = (kb <= q0 + wrow + 15) && (kb + 63 >= q0 + wrow - win + 1);
        if (active) {
            const uint32_t* Khl = Khl0 + buf * TILEF;
            const float* Vs = sm + (2 + buf) * TILEF;

            float accS[8][4] = {};
#pragma unroll
            for (int ks = 0; ks < 4; ks++) {
#pragma unroll
                for (int ni = 0; ni < 8; ni++) {
                    const uint32_t* kr = &Khl[(ni * 8 + gid) * ATS + ks * 8 + tig];
                    uint32_t bh2[2] = { kr[0],  kr[4] };
                    uint32_t bl2[2] = { kr[32], kr[36] };
                    mma_bf16(accS[ni], ahi[ks], bh2);
                    mma_bf16(accS[ni], alo[ks], bh2);
                    mma_bf16(accS[ni], ahi[ks], bl2);
                }
            }

#pragma unroll
            for (int ni = 0; ni < 8; ni++) {
#pragma unroll
                for (int j = 0; j < 4; j++) {
                    int col = ni * 8 + 2 * tig + (j & 1);
                    int r = gid + ((j >> 1) << 3);
                    int qpos = q0 + wrow + r;
                    int kpos = kb + col;
                    bool ok = (kpos <= qpos) && (kpos >= qpos - win + 1);
                    Ss[(wrow + r) * ATS + col] = ok ? accS[ni][j] : -1e30f;
                }
            }
            __syncwarp();

            {
                int srow = lane >> 1;
                int cb = (lane & 1) * 32;
                float* sp = &Ss[(wrow + srow) * ATS + cb];
                float rmax = -1e30f;
#pragma unroll
                for (int c = 0; c < 32; c++) rmax = fmaxf(rmax, sp[c]);
                rmax = fmaxf(rmax, __shfl_xor_sync(0xffffffffu, rmax, 1));
                float mnew = fmaxf(m, rmax);
                float scale, rs = 0.f;
                if (mnew <= -1e20f) {
                    scale = 1.f;
#pragma unroll
                    for (int c = 0; c < 32; c++) sp[c] = 0.f;
                } else {
                    scale = __expf(m - mnew);
#pragma unroll
                    for (int c = 0; c < 32; c++) {
                        float p = __expf(sp[c] - mnew);
                        rs += p;
                        sp[c] = to_tf32(p);
                    }
                }
                m = mnew;
                rs += __shfl_xor_sync(0xffffffffu, rs, 1);
                lsum = lsum * scale + rs;
                if ((lane & 1) == 0) scb[wrow + srow] = scale;
            }
            __syncwarp();

            {
                float sc0 = scb[wrow + gid];
                float sc1 = scb[wrow + gid + 8];
#pragma unroll
                for (int ni = 0; ni < 8; ni++) {
                    oacc[ni][0] *= sc0; oacc[ni][1] *= sc0;
                    oacc[ni][2] *= sc1; oacc[ni][3] *= sc1;
                }
            }
#pragma unroll
            for (int ks = 0; ks < 8; ks++) {
                uint32_t pa[4];
                pa[0] = __float_as_uint(Ss[(wrow + gid) * ATS + ks * 8 + tig]);
                pa[1] = __float_as_uint(Ss[(wrow + gid + 8) * ATS + ks * 8 + tig]);
                pa[2] = __float_as_uint(Ss[(wrow + gid) * ATS + ks * 8 + tig + 4]);
                pa[3] = __float_as_uint(Ss[(wrow + gid + 8) * ATS + ks * 8 + tig + 4]);
#pragma unroll
                for (int ni = 0; ni < 8; ni++) {
                    uint32_t vb[2];
                    vb[0] = __float_as_uint(Vs[(ks * 8 + tig) * ATS + ni * 8 + gid]);
                    vb[1] = __float_as_uint(Vs[(ks * 8 + tig + 4) * ATS + ni * 8 + gid]);
                    mma_tf32(oacc[ni], pa, vb);
                }
            }
        }
    }

    // ---- normalize into Ss, then store fragment-major A tiles directly ----
    if ((lane & 1) == 0) lbuf[wrow + (lane >> 1)] = lsum;
    __syncwarp();
    float li0 = 1.f / lbuf[wrow + gid];
    float li1 = 1.f / lbuf[wrow + gid + 8];

    __syncthreads();   // everyone done with Ss as P-buffer
#pragma unroll
    for (int ni = 0; ni < 8; ni++) {
        int c0 = ni * 8 + 2 * tig;
        Ss[(wrow + gid) * ATS + c0]         = oacc[ni][0] * li0;
        Ss[(wrow + gid) * ATS + c0 + 1]     = oacc[ni][1] * li0;
        Ss[(wrow + gid + 8) * ATS + c0]     = oacc[ni][2] * li1;
        Ss[(wrow + gid + 8) * ATS + c0 + 1] = oacc[ni][3] * li1;
    }
    __syncthreads();

    int rtile = b * 16 + qt;
#pragma unroll
    for (int tl = 0; tl < 4; tl++) {
        float* dtile = g_ya + ((size_t)rtile * 64 + h * 4 + tl) * 2048;
        for (int q = tid; q < 512; q += 256) {
            int gb = q >> 5;
            int g2 = gb >> 3, b2 = gb & 7;
            int ln = q & 31;
            int gd = ln >> 2, tg = ln & 3;
            const float* sp = &Ss[(b2 * 16 + gd) * ATS + tl * 16 + g2 * 8 + tg];
            float4 v;
            v.x = to_tf32(sp[0]);
            v.y = to_tf32(sp[8 * ATS]);
            v.z = to_tf32(sp[4]);
            v.w = to_tf32(sp[8 * ATS + 4]);
            *(float4*)(dtile + q * 4) = v;
        }
    }
}

// ---------------------------------------------------------------------------
extern "C" void kernel_launch(void* const* d_in, const int* in_sizes, int n_in,
                              void* d_out, int out_size)
{
    const float* x    = (const float*)d_in[0];
    const float* ve   = (const float*)d_in[1];
    const float* cosp = (const float*)d_in[2];
    const float* sinp = (const float*)d_in[3];
    const float* Wq   = (const float*)d_in[4];
    const float* Wk   = (const float*)d_in[5];
    const float* Wv   = (const float*)d_in[6];
    const float* Wo   = (const float*)d_in[7];
    const float* Wg   = (const float*)d_in[8];
    const int*   win  = (const int*)d_in[9];
    float* out = (float*)d_out;

    float *pqkv, *pxa, *pya, *pwqkvT, *pwoT;
    cudaGetSymbolAddress((void**)&pqkv, g_qkv);
    cudaGetSymbolAddress((void**)&pxa, g_xa);
    cudaGetSymbolAddress((void**)&pya, g_ya);
    cudaGetSymbolAddress((void**)&pwqkvT, g_wqkvT);
    cudaGetSymbolAddress((void**)&pwoT, g_woT);

    // fragment-major packing (tf32 rounding folded in)
    pack_a<<<dim3(64, 32), 256>>>(x, pxa);
    pack_b<<<dim3(64, 8), 256>>>(Wq, pwqkvT, 1024, 0);
    pack_b<<<dim3(64, 2), 256>>>(Wk, pwqkvT, 256, 8);
    pack_b<<<dim3(64, 2), 256>>>(Wv, pwqkvT, 256, 10);
    pack_b<<<dim3(64, 8), 256>>>(Wo, pwoT, 1024, 0);

    cudaFuncSetAttribute(gemm_fm, cudaFuncAttributeMaxDynamicSharedMemorySize, GFM_SMEM);

    // fused QKV projection (BK=32, single-sync mainloop)
    gemm_fm<<<dim3(12, 32), 256, GFM_SMEM>>>(pxa, pwqkvT, pqkv, 64, QKVLD);

    // fused v-gate + RoPE/RMSNorm + bf16 hi/lo packing
    prep_kernel<<<BB * SS * 6, 256>>>(cosp, sinp, x, ve, Wg);

    // flash attention (single-sync tile loop, fragment-major epilogue)
    {
        int smem = (4 * TILEF + 128 * ATS + 256) * sizeof(float);   // 105472 B
        cudaFuncSetAttribute(attn_tc, cudaFuncAttributeMaxDynamicSharedMemorySize, smem);
        attn_tc<<<BB * NH * (SS / 128), 256, smem>>>(win);
    }

    // output projection (reads fragment-major g_ya directly)
    gemm_fm<<<dim3(8, 32), 256, GFM_SMEM>>>(pya, pwoT, out, 64, DD);
}

// round 13
// speedup vs baseline: 1.1087x; 1.0269x over previous
#include <cuda_runtime.h>
#include <cuda_bf16.h>
#include <math.h>
#include <stdint.h>

#define BB 2
#define SS 2048
#define DD 1024
#define NH 16
#define NKV 4
#define HD 64
#define GATE_CH 12
#define EPSV 1e-6f
#define QKVLD 1536   // qkv buffer row stride: [q(1024) | k(256) | v(256)]

// ---------------- device scratch (allocation-free rule) ----------------
__device__ float    g_qkv[BB * SS * QKVLD];     // fp32 qkv (row-major)
__device__ float    g_xa[(size_t)32 * 64 * 2048];    // x, fragment-major A tiles
__device__ float    g_ya[(size_t)32 * 64 * 2048];    // attn out, fragment-major A tiles
__device__ float    g_wqkvT[(size_t)12 * 64 * 2048]; // Wq|Wk|Wv, fragment-major B tiles
__device__ float    g_woT[(size_t)8 * 64 * 2048];    // Wo, fragment-major B tiles
__device__ uint32_t g_qpk[BB * SS * NH * 64];   // q packed bf16 hi|lo
__device__ uint32_t g_kpk[BB * SS * NKV * 64];  // k packed bf16 hi|lo

// ---------------- helpers ----------------
__device__ __forceinline__ float to_tf32(float x) {
    float r; asm("cvt.rna.tf32.f32 %0, %1;" : "=f"(r) : "f"(x)); return r;
}
__device__ __forceinline__ uint32_t pack_bf16(float e, float o) {
    uint16_t a = __bfloat16_as_ushort(__float2bfloat16(e));
    uint16_t b = __bfloat16_as_ushort(__float2bfloat16(o));
    return ((uint32_t)b << 16) | a;
}
__device__ __forceinline__ void mma_tf32(float* d, const uint32_t* a, const uint32_t* b) {
    asm volatile(
        "mma.sync.aligned.m16n8k8.row.col.f32.tf32.tf32.f32 "
        "{%0,%1,%2,%3}, {%4,%5,%6,%7}, {%8,%9}, {%0,%1,%2,%3};\n"
        : "+f"(d[0]), "+f"(d[1]), "+f"(d[2]), "+f"(d[3])
        : "r"(a[0]), "r"(a[1]), "r"(a[2]), "r"(a[3]), "r"(b[0]), "r"(b[1]));
}
__device__ __forceinline__ void mma_bf16(float* d, const uint32_t* a, const uint32_t* b) {
    asm volatile(
        "mma.sync.aligned.m16n8k16.row.col.f32.bf16.bf16.f32 "
        "{%0,%1,%2,%3}, {%4,%5,%6,%7}, {%8,%9}, {%0,%1,%2,%3};\n"
        : "+f"(d[0]), "+f"(d[1]), "+f"(d[2]), "+f"(d[3])
        : "r"(a[0]), "r"(a[1]), "r"(a[2]), "r"(a[3]), "r"(b[0]), "r"(b[1]));
}
__device__ __forceinline__ void cp_async16(uint32_t saddr, const void* gptr) {
    asm volatile("cp.async.cg.shared.global [%0], [%1], 16;" :: "r"(saddr), "l"(gptr));
}
#define CP_COMMIT() asm volatile("cp.async.commit_group;")
#define CP_WAIT(n)  asm volatile("cp.async.wait_group %0;" :: "n"(n))

// ---------------------------------------------------------------------------
// pack_a: row-major [M][1024] fp32 -> fragment-major A tiles (tf32-rounded).
// ---------------------------------------------------------------------------
__global__ void pack_a(const float* __restrict__ src, float* __restrict__ dst)
{
    int kt = blockIdx.x, rt = blockIdx.y;
    float* dtile = dst + ((size_t)rt * 64 + kt) * 2048;
    const float* s = src + (size_t)rt * 128 * 1024 + kt * 16;
    for (int q = threadIdx.x; q < 512; q += 256) {
        int gb = q >> 5;
        int g = gb >> 3, b = gb & 7;
        int lane = q & 31;
        int gid = lane >> 2, tig = lane & 3;
        const float* p = s + (size_t)(b * 16 + gid) * 1024 + g * 8 + tig;
        float4 v;
        v.x = to_tf32(p[0]);
        v.y = to_tf32(p[8 * 1024]);
        v.z = to_tf32(p[4]);
        v.w = to_tf32(p[8 * 1024 + 4]);
        *(float4*)(dtile + q * 4) = v;
    }
}

// ---------------------------------------------------------------------------
// pack_b: W[K][n_src] row-major -> fragment-major B tiles at col-tile ct0+cl.
// ---------------------------------------------------------------------------
__global__ void pack_b(const float* __restrict__ W, float* __restrict__ dst,
                       int n_src, int ct0)
{
    int kt = blockIdx.x, cl = blockIdx.y;
    float* dtile = dst + ((size_t)(ct0 + cl) * 64 + kt) * 2048;
    const float* s = W + (size_t)kt * 16 * n_src + cl * 128;
    for (int q = threadIdx.x; q < 512; q += 256) {
        int plane = q >> 8;
        int q8 = q & 255;
        int gw = q8 >> 5;
        int g = gw >> 2, w = gw & 3;
        int lane = q8 & 31;
        int gid = lane >> 2, tig = lane & 3;
        const float* p = s + (size_t)(g * 8 + tig + plane * 4) * n_src + w * 32 + gid;
        float4 v;
        v.x = to_tf32(p[0]);
        v.y = to_tf32(p[8]);
        v.z = to_tf32(p[16]);
        v.w = to_tf32(p[24]);
        *(float4*)(dtile + q * 4) = v;
    }
}

// ---------------------------------------------------------------------------
// gemm_fm: tf32 HMMA GEMM on fragment-major tiles, BK=32, 3-stage cp.async,
// single __syncthreads per mainloop iteration. (unchanged from R12)
// ---------------------------------------------------------------------------
#define GFM_SMEM 98304
__global__ __launch_bounds__(256, 2) void gemm_fm(
    const float* __restrict__ At, const float* __restrict__ Bt,
    float* __restrict__ C, int nkt, int ldc)
{
    extern __shared__ float smg[];
    uint32_t smb = (uint32_t)__cvta_generic_to_shared(smg);
    const int tid = threadIdx.x;
    const int lane = tid & 31, wid = tid >> 5;
    const int gid = lane >> 2, tig = lane & 3;
    const int wm4 = (wid >> 2) * 4;
    const int wn5 = wid & 3;
    const int rowBase = blockIdx.y * 128, colBase = blockIdx.x * 128;

    const float* Abase = At + (size_t)blockIdx.y * nkt * 2048 + tid * 8;
    const float* Bbase = Bt + (size_t)blockIdx.x * nkt * 2048 + tid * 8;

#define FM_STAGE(p, s) do { \
    uint32_t _d = smb + (s) * 32768 + tid * 32; \
    const float* _a = Abase + (size_t)(p) * 4096; \
    const float* _b = Bbase + (size_t)(p) * 4096; \
    cp_async16(_d,            _a);        cp_async16(_d + 16,           _a + 4); \
    cp_async16(_d + 8192,     _a + 2048); cp_async16(_d + 8192 + 16,    _a + 2052); \
    cp_async16(_d + 16384,    _b);        cp_async16(_d + 16384 + 16,   _b + 4); \
    cp_async16(_d + 24576,    _b + 2048); cp_async16(_d + 24576 + 16,   _b + 2052); \
    CP_COMMIT(); \
} while (0)

    FM_STAGE(0, 0);
    FM_STAGE(1, 1);

    float acc[4][4][4] = {};
    const int np = nkt >> 1;
    for (int it = 0; it < np; it++) {
        const int s = it % 3;
        if (it + 1 < np) { CP_WAIT(1); } else { CP_WAIT(0); }
        __syncthreads();
        if (it + 2 < np) FM_STAGE(it + 2, (it + 2) % 3);

#pragma unroll
        for (int t01 = 0; t01 < 2; t01++) {
            const uint4* As4 = (const uint4*)(smg + s * 8192 + t01 * 2048);
            const uint4* Bs4 = (const uint4*)(smg + s * 8192 + 4096 + t01 * 2048);
#pragma unroll
            for (int g = 0; g < 2; g++) {
                uint4 afr[4];
#pragma unroll
                for (int mi = 0; mi < 4; mi++)
                    afr[mi] = As4[(g * 8 + wm4 + mi) * 32 + lane];
                uint4 b0 = Bs4[(g * 4 + wn5) * 32 + lane];
                uint4 b1 = Bs4[256 + (g * 4 + wn5) * 32 + lane];
                uint32_t bf[4][2] = {
                    {b0.x, b1.x}, {b0.y, b1.y}, {b0.z, b1.z}, {b0.w, b1.w}};
#pragma unroll
                for (int mi = 0; mi < 4; mi++) {
                    const uint32_t* af = (const uint32_t*)&afr[mi];
#pragma unroll
                    for (int ni = 0; ni < 4; ni++)
                        mma_tf32(acc[mi][ni], af, bf[ni]);
                }
            }
        }
    }

    const int warp_m = wm4 * 16, warp_n = wn5 * 32;
#pragma unroll
    for (int mi = 0; mi < 4; mi++) {
#pragma unroll
        for (int ni = 0; ni < 4; ni++) {
            int row = rowBase + warp_m + mi * 16 + gid;
            int col = colBase + warp_n + ni * 8 + 2 * tig;
            *(float2*)(C + (size_t)row * ldc + col) =
                make_float2(acc[mi][ni][0], acc[mi][ni][1]);
            *(float2*)(C + (size_t)(row + 8) * ldc + col) =
                make_float2(acc[mi][ni][2], acc[mi][ni][3]);
        }
    }
}

// ---------------------------------------------------------------------------
// Fused prep, 256-thread blocks (4 head-units per block). (unchanged)
// ---------------------------------------------------------------------------
__global__ void prep_kernel(const float* __restrict__ cosp,
                            const float* __restrict__ sinp,
                            const float* __restrict__ x,
                            const float* __restrict__ ve,
                            const float* __restrict__ Wg)
{
    int blk = blockIdx.x;
    int grp = blk % 6;
    int bs = blk / 6;
    int unit = threadIdx.x >> 6;
    int d = threadIdx.x & 63;
    int hh = grp * 4 + unit;

    if (hh >= NH + NKV) {
        int kvh = hh - (NH + NKV);
        const float* xr = x + (size_t)bs * DD;
        float g = 0.f;
#pragma unroll
        for (int c = 0; c < GATE_CH; c++) g += xr[c] * Wg[c * NKV + kvh];
        g = 3.f / (1.f + __expf(-g));
        float* vp = &g_qkv[(size_t)bs * QKVLD + 1280 + kvh * HD + d];
        *vp = to_tf32(*vp + g * ve[(size_t)bs * (NKV * HD) + kvh * HD + d]);
        return;
    }

    int s = bs % SS;
    const float* ptr = g_qkv + (size_t)bs * QKVLD +
                       ((hh < NH) ? hh * HD : 1024 + (hh - NH) * HD);

    int half = d & 31;
    float c  = cosp[s * 32 + half];
    float sn = sinp[s * 32 + half];
    float x1 = ptr[half];
    float x2 = ptr[half + 32];
    float rot = (d < 32) ? (x1 * c + x2 * sn) : (-x1 * sn + x2 * c);

    __shared__ float red[4][2];
    float v = rot * rot;
#pragma unroll
    for (int o = 16; o > 0; o >>= 1) v += __shfl_xor_sync(0xffffffffu, v, o);
    if ((d & 31) == 0) red[unit][d >> 5] = v;
    __syncthreads();
    float total = red[unit][0] + red[unit][1];
    float r = rsqrtf(total * (1.f / HD) + EPSV) * 1.2f;
    float val = rot * r;
    if (hh < NH) val *= 0.125f;

    float hif = __bfloat162float(__float2bfloat16(val));
    float lof = val - hif;
    float val_o = __shfl_down_sync(0xffffffffu, val, 1);
    float lof_o = __shfl_down_sync(0xffffffffu, lof, 1);

    if ((d & 1) == 0) {
        uint32_t hp = pack_bf16(val, val_o);
        uint32_t lp = pack_bf16(lof, lof_o);
        uint32_t* out = (hh < NH)
            ? &g_qpk[((size_t)bs * NH + hh) * 64]
            : &g_kpk[((size_t)bs * NKV + (hh - NH)) * 64];
        out[d >> 1]        = hp;
        out[32 + (d >> 1)] = lp;
    }
}

// ---------------------------------------------------------------------------
// Tensor-core flash attention, 128 queries/CTA, 8 warps.
// REGISTER-RESIDENT softmax: mask/max/exp/sum/rescale on accS in registers,
// quad shfl reductions; P written to smem once. No scb/lbuf.
// ---------------------------------------------------------------------------
#define ATS 68
#define TILEF (64 * ATS)
__global__ __launch_bounds__(256, 2) void attn_tc(const int* __restrict__ winp)
{
    const int win = *winp;
    int bid = blockIdx.x;
    int qt = bid & 15;
    int bh = bid >> 4;
    int h = bh % NH;
    int b = bh / NH;
    int q0 = qt * 128;
    int kvh = h / (NH / NKV);

    const int tid = threadIdx.x;
    const int lane = tid & 31;
    const int warp = tid >> 5;
    const int wrow = warp * 16;
    const int gid = lane >> 2;
    const int tig = lane & 3;

    extern __shared__ float sm[];
    uint32_t* Khl0 = (uint32_t*)sm;
    float* Ss = sm + 4 * TILEF;
    uint32_t smbase = (uint32_t)__cvta_generic_to_shared(sm);

    const int st_r  = tid >> 4;
    const int st_c4 = (tid & 15) * 4;

    {
        uint32_t* Qs = (uint32_t*)Ss;
        for (int i = tid; i < 128 * 16; i += 256) {
            int r = i >> 4;
            int c4 = (i & 15) * 4;
            *(uint4*)&Qs[r * ATS + c4] =
                *(const uint4*)(g_qpk + ((size_t)(b * SS + q0 + r) * NH + h) * 64 + c4);
        }
    }
    __syncthreads();

    uint32_t ahi[4][4], alo[4][4];
    {
        const uint32_t* Qs = (const uint32_t*)Ss;
#pragma unroll
        for (int ks = 0; ks < 4; ks++) {
            int cb = ks * 8 + tig;
            ahi[ks][0] = Qs[(wrow + gid) * ATS + cb];
            ahi[ks][1] = Qs[(wrow + gid + 8) * ATS + cb];
            ahi[ks][2] = Qs[(wrow + gid) * ATS + cb + 4];
            ahi[ks][3] = Qs[(wrow + gid + 8) * ATS + cb + 4];
            alo[ks][0] = Qs[(wrow + gid) * ATS + 32 + cb];
            alo[ks][1] = Qs[(wrow + gid + 8) * ATS + 32 + cb];
            alo[ks][2] = Qs[(wrow + gid) * ATS + 32 + cb + 4];
            alo[ks][3] = Qs[(wrow + gid + 8) * ATS + 32 + cb + 4];
        }
    }

    float m0 = -1e30f, m1 = -1e30f, lsum0 = 0.f, lsum1 = 0.f;
    float oacc[8][4] = {};

    int kmin = q0 - win + 1;
    if (kmin < 0) kmin = 0;
    int t0 = kmin >> 6;
    int t1 = (q0 + 127) >> 6;

#define AT_STAGE(tt, bf) do { \
    int _kb = (tt) << 6; \
    const uint32_t* _ks = g_kpk + ((size_t)(b * SS + _kb + st_r) * NKV + kvh) * 64 + st_c4; \
    const float* _vs = g_qkv + (size_t)(b * SS + _kb + st_r) * QKVLD + 1280 + kvh * HD + st_c4; \
    uint32_t _kd = smbase + ((bf) * TILEF + st_r * ATS + st_c4) * 4; \
    uint32_t _vd = smbase + ((2 + (bf)) * TILEF + st_r * ATS + st_c4) * 4; \
    _Pragma("unroll") \
    for (int _j = 0; _j < 4; _j++) { \
        cp_async16(_kd + _j * 16 * ATS * 4, _ks + (size_t)_j * 16 * NKV * 64); \
        cp_async16(_vd + _j * 16 * ATS * 4, _vs + (size_t)_j * 16 * QKVLD); \
    } \
    CP_COMMIT(); \
} while (0)

    AT_STAGE(t0, 0);

    for (int t = t0; t <= t1; t++) {
        int kb = t << 6;
        const int buf = (t - t0) & 1;
        CP_WAIT(0);
        __syncthreads();   // tile t visible; everyone done reading buf^1
        if (t < t1) AT_STAGE(t + 1, buf ^ 1);

        bool active = (kb <= q0 + wrow + 15) && (kb + 63 >= q0 + wrow - win + 1);
        if (active) {
            const uint32_t* Khl = Khl0 + buf * TILEF;
            const float* Vs = sm + (2 + buf) * TILEF;

            // ---- S = Q @ K^T : bf16 hi/lo ----
            float accS[8][4] = {};
#pragma unroll
            for (int ks = 0; ks < 4; ks++) {
#pragma unroll
                for (int ni = 0; ni < 8; ni++) {
                    const uint32_t* kr = &Khl[(ni * 8 + gid) * ATS + ks * 8 + tig];
                    uint32_t bh2[2] = { kr[0],  kr[4] };
                    uint32_t bl2[2] = { kr[32], kr[36] };
                    mma_bf16(accS[ni], ahi[ks], bh2);
                    mma_bf16(accS[ni], alo[ks], bh2);
                    mma_bf16(accS[ni], ahi[ks], bl2);
                }
            }

            // ---- register softmax: mask + row max ----
            int qpos0 = q0 + wrow + gid;
            int qpos1 = qpos0 + 8;
            float mx0 = -1e30f, mx1 = -1e30f;
#pragma unroll
            for (int ni = 0; ni < 8; ni++) {
#pragma unroll
                for (int j = 0; j < 4; j++) {
                    int kpos = kb + ni * 8 + 2 * tig + (j & 1);
                    int qp = (j < 2) ? qpos0 : qpos1;
                    bool ok = (kpos <= qp) && (kpos >= qp - win + 1);
                    float s = ok ? accS[ni][j] : -1e30f;
                    accS[ni][j] = s;
                    if (j < 2) mx0 = fmaxf(mx0, s);
                    else       mx1 = fmaxf(mx1, s);
                }
            }
            mx0 = fmaxf(mx0, __shfl_xor_sync(0xffffffffu, mx0, 1));
            mx0 = fmaxf(mx0, __shfl_xor_sync(0xffffffffu, mx0, 2));
            mx1 = fmaxf(mx1, __shfl_xor_sync(0xffffffffu, mx1, 1));
            mx1 = fmaxf(mx1, __shfl_xor_sync(0xffffffffu, mx1, 2));

            float mnew0 = fmaxf(m0, mx0), mnew1 = fmaxf(m1, mx1);
            bool dead0 = (mnew0 <= -1e20f), dead1 = (mnew1 <= -1e20f);
            float scale0 = dead0 ? 1.f : __expf(m0 - mnew0);
            float scale1 = dead1 ? 1.f : __expf(m1 - mnew1);

            // ---- exp + row sum + write P (tf32) to smem ----
            float rs0 = 0.f, rs1 = 0.f;
#pragma unroll
            for (int ni = 0; ni < 8; ni++) {
                int c0 = ni * 8 + 2 * tig;
#pragma unroll
                for (int j = 0; j < 4; j++) {
                    bool lo = (j < 2);
                    float p = lo ? (dead0 ? 0.f : __expf(accS[ni][j] - mnew0))
                                 : (dead1 ? 0.f : __expf(accS[ni][j] - mnew1));
                    if (lo) rs0 += p; else rs1 += p;
                    int row = lo ? (wrow + gid) : (wrow + gid + 8);
                    Ss[row * ATS + c0 + (j & 1)] = to_tf32(p);
                }
            }
            rs0 += __shfl_xor_sync(0xffffffffu, rs0, 1);
            rs0 += __shfl_xor_sync(0xffffffffu, rs0, 2);
            rs1 += __shfl_xor_sync(0xffffffffu, rs1, 1);
            rs1 += __shfl_xor_sync(0xffffffffu, rs1, 2);

            m0 = mnew0; m1 = mnew1;
            lsum0 = lsum0 * scale0 + rs0;
            lsum1 = lsum1 * scale1 + rs1;

            // ---- rescale O, then O += P @ V ----
#pragma unroll
            for (int ni = 0; ni < 8; ni++) {
                oacc[ni][0] *= scale0; oacc[ni][1] *= scale0;
                oacc[ni][2] *= scale1; oacc[ni][3] *= scale1;
            }
            __syncwarp();
#pragma unroll
            for (int ks = 0; ks < 8; ks++) {
                uint32_t pa[4];
                pa[0] = __float_as_uint(Ss[(wrow + gid) * ATS + ks * 8 + tig]);
                pa[1] = __float_as_uint(Ss[(wrow + gid + 8) * ATS + ks * 8 + tig]);
                pa[2] = __float_as_uint(Ss[(wrow + gid) * ATS + ks * 8 + tig + 4]);
                pa[3] = __float_as_uint(Ss[(wrow + gid + 8) * ATS + ks * 8 + tig + 4]);
#pragma unroll
                for (int ni = 0; ni < 8; ni++) {
                    uint32_t vb[2];
                    vb[0] = __float_as_uint(Vs[(ks * 8 + tig) * ATS + ni * 8 + gid]);
                    vb[1] = __float_as_uint(Vs[(ks * 8 + tig + 4) * ATS + ni * 8 + gid]);
                    mma_tf32(oacc[ni], pa, vb);
                }
            }
        }
    }

    // ---- normalize into Ss, then store fragment-major A tiles directly ----
    float li0 = 1.f / lsum0;
    float li1 = 1.f / lsum1;

    __syncthreads();   // everyone done with Ss as P-buffer
#pragma unroll
    for (int ni = 0; ni < 8; ni++) {
        int c0 = ni * 8 + 2 * tig;
        Ss[(wrow + gid) * ATS + c0]         = oacc[ni][0] * li0;
        Ss[(wrow + gid) * ATS + c0 + 1]     = oacc[ni][1] * li0;
        Ss[(wrow + gid + 8) * ATS + c0]     = oacc[ni][2] * li1;
        Ss[(wrow + gid + 8) * ATS + c0 + 1] = oacc[ni][3] * li1;
    }
    __syncthreads();

    int rtile = b * 16 + qt;
#pragma unroll
    for (int tl = 0; tl < 4; tl++) {
        float* dtile = g_ya + ((size_t)rtile * 64 + h * 4 + tl) * 2048;
        for (int q = tid; q < 512; q += 256) {
            int gb = q >> 5;
            int g2 = gb >> 3, b2 = gb & 7;
            int ln = q & 31;
            int gd = ln >> 2, tg = ln & 3;
            const float* sp = &Ss[(b2 * 16 + gd) * ATS + tl * 16 + g2 * 8 + tg];
            float4 v;
            v.x = to_tf32(sp[0]);
            v.y = to_tf32(sp[8 * ATS]);
            v.z = to_tf32(sp[4]);
            v.w = to_tf32(sp[8 * ATS + 4]);
            *(float4*)(dtile + q * 4) = v;
        }
    }
}

// ---------------------------------------------------------------------------
extern "C" void kernel_launch(void* const* d_in, const int* in_sizes, int n_in,
                              void* d_out, int out_size)
{
    const float* x    = (const float*)d_in[0];
    const float* ve   = (const float*)d_in[1];
    const float* cosp = (const float*)d_in[2];
    const float* sinp = (const float*)d_in[3];
    const float* Wq   = (const float*)d_in[4];
    const float* Wk   = (const float*)d_in[5];
    const float* Wv   = (const float*)d_in[6];
    const float* Wo   = (const float*)d_in[7];
    const float* Wg   = (const float*)d_in[8];
    const int*   win  = (const int*)d_in[9];
    float* out = (float*)d_out;

    float *pqkv, *pxa, *pya, *pwqkvT, *pwoT;
    cudaGetSymbolAddress((void**)&pqkv, g_qkv);
    cudaGetSymbolAddress((void**)&pxa, g_xa);
    cudaGetSymbolAddress((void**)&pya, g_ya);
    cudaGetSymbolAddress((void**)&pwqkvT, g_wqkvT);
    cudaGetSymbolAddress((void**)&pwoT, g_woT);

    // fragment-major packing (tf32 rounding folded in)
    pack_a<<<dim3(64, 32), 256>>>(x, pxa);
    pack_b<<<dim3(64, 8), 256>>>(Wq, pwqkvT, 1024, 0);
    pack_b<<<dim3(64, 2), 256>>>(Wk, pwqkvT, 256, 8);
    pack_b<<<dim3(64, 2), 256>>>(Wv, pwqkvT, 256, 10);
    pack_b<<<dim3(64, 8), 256>>>(Wo, pwoT, 1024, 0);

    cudaFuncSetAttribute(gemm_fm, cudaFuncAttributeMaxDynamicSharedMemorySize, GFM_SMEM);

    // fused QKV projection
    gemm_fm<<<dim3(12, 32), 256, GFM_SMEM>>>(pxa, pwqkvT, pqkv, 64, QKVLD);

    // fused v-gate + RoPE/RMSNorm + bf16 hi/lo packing
    prep_kernel<<<BB * SS * 6, 256>>>(cosp, sinp, x, ve, Wg);

    // flash attention (register-resident softmax)
    {
        int smem = (4 * TILEF + 128 * ATS) * sizeof(float);   // 104448 B
        cudaFuncSetAttribute(attn_tc, cudaFuncAttributeMaxDynamicSharedMemorySize, smem);
        attn_tc<<<BB * NH * (SS / 128), 256, smem>>>(win);
    }

    // output projection (reads fragment-major g_ya directly)
    gemm_fm<<<dim3(8, 32), 256, GFM_SMEM>>>(pya, pwoT, out, 64, DD);
}

// round 14
// speedup vs baseline: 1.1314x; 1.0205x over previous
#include <cuda_runtime.h>
#include <cuda_bf16.h>
#include <math.h>
#include <stdint.h>

#define BB 2
#define SS 2048
#define DD 1024
#define NH 16
#define NKV 4
#define HD 64
#define GATE_CH 12
#define EPSV 1e-6f
#define QKVLD 1536   // qkv buffer row stride: [q(1024) | k(256) | v(256)]

// ---------------- device scratch (allocation-free rule) ----------------
__device__ float    g_qkv[BB * SS * QKVLD];     // qkv partial 0 / combined v
__device__ float    g_qkv2[BB * SS * QKVLD];    // qkv partial 1 (split-K)
__device__ float    g_xa[(size_t)32 * 64 * 2048];    // x, fragment-major A tiles
__device__ float    g_ya[(size_t)32 * 64 * 2048];    // attn out, fragment-major A tiles
__device__ float    g_wqkvT[(size_t)12 * 64 * 2048]; // Wq|Wk|Wv, fragment-major B tiles
__device__ float    g_woT[(size_t)8 * 64 * 2048];    // Wo, fragment-major B tiles
__device__ uint32_t g_qpk[BB * SS * NH * 64];   // q packed bf16 hi|lo
__device__ uint32_t g_kpk[BB * SS * NKV * 64];  // k packed bf16 hi|lo

// ---------------- helpers ----------------
__device__ __forceinline__ float to_tf32(float x) {
    float r; asm("cvt.rna.tf32.f32 %0, %1;" : "=f"(r) : "f"(x)); return r;
}
__device__ __forceinline__ uint32_t pack_bf16(float e, float o) {
    uint16_t a = __bfloat16_as_ushort(__float2bfloat16(e));
    uint16_t b = __bfloat16_as_ushort(__float2bfloat16(o));
    return ((uint32_t)b << 16) | a;
}
__device__ __forceinline__ void mma_tf32(float* d, const uint32_t* a, const uint32_t* b) {
    asm volatile(
        "mma.sync.aligned.m16n8k8.row.col.f32.tf32.tf32.f32 "
        "{%0,%1,%2,%3}, {%4,%5,%6,%7}, {%8,%9}, {%0,%1,%2,%3};\n"
        : "+f"(d[0]), "+f"(d[1]), "+f"(d[2]), "+f"(d[3])
        : "r"(a[0]), "r"(a[1]), "r"(a[2]), "r"(a[3]), "r"(b[0]), "r"(b[1]));
}
__device__ __forceinline__ void mma_bf16(float* d, const uint32_t* a, const uint32_t* b) {
    asm volatile(
        "mma.sync.aligned.m16n8k16.row.col.f32.bf16.bf16.f32 "
        "{%0,%1,%2,%3}, {%4,%5,%6,%7}, {%8,%9}, {%0,%1,%2,%3};\n"
        : "+f"(d[0]), "+f"(d[1]), "+f"(d[2]), "+f"(d[3])
        : "r"(a[0]), "r"(a[1]), "r"(a[2]), "r"(a[3]), "r"(b[0]), "r"(b[1]));
}
__device__ __forceinline__ void cp_async16(uint32_t saddr, const void* gptr) {
    asm volatile("cp.async.cg.shared.global [%0], [%1], 16;" :: "r"(saddr), "l"(gptr));
}
#define CP_COMMIT() asm volatile("cp.async.commit_group;")
#define CP_WAIT(n)  asm volatile("cp.async.wait_group %0;" :: "n"(n))

// ---------------------------------------------------------------------------
// pack_a: row-major [M][1024] fp32 -> fragment-major A tiles (tf32-rounded).
// ---------------------------------------------------------------------------
__global__ void pack_a(const float* __restrict__ src, float* __restrict__ dst)
{
    int kt = blockIdx.x, rt = blockIdx.y;
    float* dtile = dst + ((size_t)rt * 64 + kt) * 2048;
    const float* s = src + (size_t)rt * 128 * 1024 + kt * 16;
    for (int q = threadIdx.x; q < 512; q += 256) {
        int gb = q >> 5;
        int g = gb >> 3, b = gb & 7;
        int lane = q & 31;
        int gid = lane >> 2, tig = lane & 3;
        const float* p = s + (size_t)(b * 16 + gid) * 1024 + g * 8 + tig;
        float4 v;
        v.x = to_tf32(p[0]);
        v.y = to_tf32(p[8 * 1024]);
        v.z = to_tf32(p[4]);
        v.w = to_tf32(p[8 * 1024 + 4]);
        *(float4*)(dtile + q * 4) = v;
    }
}

// ---------------------------------------------------------------------------
// pack_bqkv: merged Wq|Wk|Wv pack. grid (64, 12): cl<8 Wq, cl 8-9 Wk, 10-11 Wv.
// ---------------------------------------------------------------------------
__global__ void pack_bqkv(const float* __restrict__ Wq,
                          const float* __restrict__ Wk,
                          const float* __restrict__ Wv,
                          float* __restrict__ dst)
{
    int kt = blockIdx.x, ct = blockIdx.y;
    const float* W;
    int n_src, cl;
    if (ct < 8)       { W = Wq; n_src = 1024; cl = ct; }
    else if (ct < 10) { W = Wk; n_src = 256;  cl = ct - 8; }
    else              { W = Wv; n_src = 256;  cl = ct - 10; }

    float* dtile = dst + ((size_t)ct * 64 + kt) * 2048;
    const float* s = W + (size_t)kt * 16 * n_src + cl * 128;
    for (int q = threadIdx.x; q < 512; q += 256) {
        int plane = q >> 8;
        int q8 = q & 255;
        int gw = q8 >> 5;
        int g = gw >> 2, w = gw & 3;
        int lane = q8 & 31;
        int gid = lane >> 2, tig = lane & 3;
        const float* p = s + (size_t)(g * 8 + tig + plane * 4) * n_src + w * 32 + gid;
        float4 v;
        v.x = to_tf32(p[0]);
        v.y = to_tf32(p[8]);
        v.z = to_tf32(p[16]);
        v.w = to_tf32(p[24]);
        *(float4*)(dtile + q * 4) = v;
    }
}

// pack_b (single matrix) for Wo
__global__ void pack_b(const float* __restrict__ W, float* __restrict__ dst,
                       int n_src, int ct0)
{
    int kt = blockIdx.x, cl = blockIdx.y;
    float* dtile = dst + ((size_t)(ct0 + cl) * 64 + kt) * 2048;
    const float* s = W + (size_t)kt * 16 * n_src + cl * 128;
    for (int q = threadIdx.x; q < 512; q += 256) {
        int plane = q >> 8;
        int q8 = q & 255;
        int gw = q8 >> 5;
        int g = gw >> 2, w = gw & 3;
        int lane = q8 & 31;
        int gid = lane >> 2, tig = lane & 3;
        const float* p = s + (size_t)(g * 8 + tig + plane * 4) * n_src + w * 32 + gid;
        float4 v;
        v.x = to_tf32(p[0]);
        v.y = to_tf32(p[8]);
        v.z = to_tf32(p[16]);
        v.w = to_tf32(p[24]);
        *(float4*)(dtile + q * 4) = v;
    }
}

// ---------------------------------------------------------------------------
// gemm_fm: tf32 HMMA GEMM on fragment-major tiles, BK=32, 3-stage cp.async,
// single sync/iter. blockIdx.z selects K-half (split-K): z*32 tile offset,
// output to C0 (z=0) or C1 (z=1). nkt = tiles processed per CTA.
// A/B row-tile stride is 64 k-tiles (full K).
// ---------------------------------------------------------------------------
#define GFM_SMEM 98304
__global__ __launch_bounds__(256, 2) void gemm_fm(
    const float* __restrict__ At, const float* __restrict__ Bt,
    float* __restrict__ C0, float* __restrict__ C1, int nkt, int ldc)
{
    extern __shared__ float smg[];
    uint32_t smb = (uint32_t)__cvta_generic_to_shared(smg);
    const int tid = threadIdx.x;
    const int lane = tid & 31, wid = tid >> 5;
    const int gid = lane >> 2, tig = lane & 3;
    const int wm4 = (wid >> 2) * 4;
    const int wn5 = wid & 3;
    const int rowBase = blockIdx.y * 128, colBase = blockIdx.x * 128;

    float* C = (blockIdx.z == 0) ? C0 : C1;
    const float* Abase = At + ((size_t)blockIdx.y * 64 + blockIdx.z * 32) * 2048 + tid * 8;
    const float* Bbase = Bt + ((size_t)blockIdx.x * 64 + blockIdx.z * 32) * 2048 + tid * 8;

#define FM_STAGE(p, s) do { \
    uint32_t _d = smb + (s) * 32768 + tid * 32; \
    const float* _a = Abase + (size_t)(p) * 4096; \
    const float* _b = Bbase + (size_t)(p) * 4096; \
    cp_async16(_d,            _a);        cp_async16(_d + 16,           _a + 4); \
    cp_async16(_d + 8192,     _a + 2048); cp_async16(_d + 8192 + 16,    _a + 2052); \
    cp_async16(_d + 16384,    _b);        cp_async16(_d + 16384 + 16,   _b + 4); \
    cp_async16(_d + 24576,    _b + 2048); cp_async16(_d + 24576 + 16,   _b + 2052); \
    CP_COMMIT(); \
} while (0)

    FM_STAGE(0, 0);
    FM_STAGE(1, 1);

    float acc[4][4][4] = {};
    const int np = nkt >> 1;
    for (int it = 0; it < np; it++) {
        const int s = it % 3;
        if (it + 1 < np) { CP_WAIT(1); } else { CP_WAIT(0); }
        __syncthreads();
        if (it + 2 < np) FM_STAGE(it + 2, (it + 2) % 3);

#pragma unroll
        for (int t01 = 0; t01 < 2; t01++) {
            const uint4* As4 = (const uint4*)(smg + s * 8192 + t01 * 2048);
            const uint4* Bs4 = (const uint4*)(smg + s * 8192 + 4096 + t01 * 2048);
#pragma unroll
            for (int g = 0; g < 2; g++) {
                uint4 afr[4];
#pragma unroll
                for (int mi = 0; mi < 4; mi++)
                    afr[mi] = As4[(g * 8 + wm4 + mi) * 32 + lane];
                uint4 b0 = Bs4[(g * 4 + wn5) * 32 + lane];
                uint4 b1 = Bs4[256 + (g * 4 + wn5) * 32 + lane];
                uint32_t bf[4][2] = {
                    {b0.x, b1.x}, {b0.y, b1.y}, {b0.z, b1.z}, {b0.w, b1.w}};
#pragma unroll
                for (int mi = 0; mi < 4; mi++) {
                    const uint32_t* af = (const uint32_t*)&afr[mi];
#pragma unroll
                    for (int ni = 0; ni < 4; ni++)
                        mma_tf32(acc[mi][ni], af, bf[ni]);
                }
            }
        }
    }

    const int warp_m = wm4 * 16, warp_n = wn5 * 32;
#pragma unroll
    for (int mi = 0; mi < 4; mi++) {
#pragma unroll
        for (int ni = 0; ni < 4; ni++) {
            int row = rowBase + warp_m + mi * 16 + gid;
            int col = colBase + warp_n + ni * 8 + 2 * tig;
            *(float2*)(C + (size_t)row * ldc + col) =
                make_float2(acc[mi][ni][0], acc[mi][ni][1]);
            *(float2*)(C + (size_t)(row + 8) * ldc + col) =
                make_float2(acc[mi][ni][2], acc[mi][ni][3]);
        }
    }
}

// ---------------------------------------------------------------------------
// Fused prep (combines split-K partials): rope units read p1+p2; vgate writes
// combined v back into g_qkv. 256-thread blocks, 4 head-units per block.
// ---------------------------------------------------------------------------
__global__ void prep_kernel(const float* __restrict__ cosp,
                            const float* __restrict__ sinp,
                            const float* __restrict__ x,
                            const float* __restrict__ ve,
                            const float* __restrict__ Wg)
{
    int blk = blockIdx.x;
    int grp = blk % 6;
    int bs = blk / 6;
    int unit = threadIdx.x >> 6;
    int d = threadIdx.x & 63;
    int hh = grp * 4 + unit;

    if (hh >= NH + NKV) {
        int kvh = hh - (NH + NKV);
        const float* xr = x + (size_t)bs * DD;
        float g = 0.f;
#pragma unroll
        for (int c = 0; c < GATE_CH; c++) g += xr[c] * Wg[c * NKV + kvh];
        g = 3.f / (1.f + __expf(-g));
        size_t off = (size_t)bs * QKVLD + 1280 + kvh * HD + d;
        float v = g_qkv[off] + g_qkv2[off];
        g_qkv[off] = to_tf32(v + g * ve[(size_t)bs * (NKV * HD) + kvh * HD + d]);
        return;
    }

    int s = bs % SS;
    size_t base = (size_t)bs * QKVLD + ((hh < NH) ? hh * HD : 1024 + (hh - NH) * HD);

    int half = d & 31;
    float c  = cosp[s * 32 + half];
    float sn = sinp[s * 32 + half];
    float x1 = g_qkv[base + half]      + g_qkv2[base + half];
    float x2 = g_qkv[base + half + 32] + g_qkv2[base + half + 32];
    float rot = (d < 32) ? (x1 * c + x2 * sn) : (-x1 * sn + x2 * c);

    __shared__ float red[4][2];
    float v = rot * rot;
#pragma unroll
    for (int o = 16; o > 0; o >>= 1) v += __shfl_xor_sync(0xffffffffu, v, o);
    if ((d & 31) == 0) red[unit][d >> 5] = v;
    __syncthreads();
    float total = red[unit][0] + red[unit][1];
    float r = rsqrtf(total * (1.f / HD) + EPSV) * 1.2f;
    float val = rot * r;
    if (hh < NH) val *= 0.125f;

    float hif = __bfloat162float(__float2bfloat16(val));
    float lof = val - hif;
    float val_o = __shfl_down_sync(0xffffffffu, val, 1);
    float lof_o = __shfl_down_sync(0xffffffffu, lof, 1);

    if ((d & 1) == 0) {
        uint32_t hp = pack_bf16(val, val_o);
        uint32_t lp = pack_bf16(lof, lof_o);
        uint32_t* out = (hh < NH)
            ? &g_qpk[((size_t)bs * NH + hh) * 64]
            : &g_kpk[((size_t)bs * NKV + (hh - NH)) * 64];
        out[d >> 1]        = hp;
        out[32 + (d >> 1)] = lp;
    }
}

// ---------------------------------------------------------------------------
// Tensor-core flash attention, 128 queries/CTA, 8 warps, register softmax.
// Heavy-first CTA order: qt = 15 - (bid & 15).
// ---------------------------------------------------------------------------
#define ATS 68
#define TILEF (64 * ATS)
__global__ __launch_bounds__(256, 2) void attn_tc(const int* __restrict__ winp)
{
    const int win = *winp;
    int bid = blockIdx.x;
    int qt = 15 - (bid & 15);        // heavy CTAs first
    int bh = bid >> 4;
    int h = bh % NH;
    int b = bh / NH;
    int q0 = qt * 128;
    int kvh = h / (NH / NKV);

    const int tid = threadIdx.x;
    const int lane = tid & 31;
    const int warp = tid >> 5;
    const int wrow = warp * 16;
    const int gid = lane >> 2;
    const int tig = lane & 3;

    extern __shared__ float sm[];
    uint32_t* Khl0 = (uint32_t*)sm;
    float* Ss = sm + 4 * TILEF;
    uint32_t smbase = (uint32_t)__cvta_generic_to_shared(sm);

    const int st_r  = tid >> 4;
    const int st_c4 = (tid & 15) * 4;

    {
        uint32_t* Qs = (uint32_t*)Ss;
        for (int i = tid; i < 128 * 16; i += 256) {
            int r = i >> 4;
            int c4 = (i & 15) * 4;
            *(uint4*)&Qs[r * ATS + c4] =
                *(const uint4*)(g_qpk + ((size_t)(b * SS + q0 + r) * NH + h) * 64 + c4);
        }
    }
    __syncthreads();

    uint32_t ahi[4][4], alo[4][4];
    {
        const uint32_t* Qs = (const uint32_t*)Ss;
#pragma unroll
        for (int ks = 0; ks < 4; ks++) {
            int cb = ks * 8 + tig;
            ahi[ks][0] = Qs[(wrow + gid) * ATS + cb];
            ahi[ks][1] = Qs[(wrow + gid + 8) * ATS + cb];
            ahi[ks][2] = Qs[(wrow + gid) * ATS + cb + 4];
            ahi[ks][3] = Qs[(wrow + gid + 8) * ATS + cb + 4];
            alo[ks][0] = Qs[(wrow + gid) * ATS + 32 + cb];
            alo[ks][1] = Qs[(wrow + gid + 8) * ATS + 32 + cb];
            alo[ks][2] = Qs[(wrow + gid) * ATS + 32 + cb + 4];
            alo[ks][3] = Qs[(wrow + gid + 8) * ATS + 32 + cb + 4];
        }
    }

    float m0 = -1e30f, m1 = -1e30f, lsum0 = 0.f, lsum1 = 0.f;
    float oacc[8][4] = {};

    int kmin = q0 - win + 1;
    if (kmin < 0) kmin = 0;
    int t0 = kmin >> 6;
    int t1 = (q0 + 127) >> 6;

#define AT_STAGE(tt, bf) do { \
    int _kb = (tt) << 6; \
    const uint32_t* _ks = g_kpk + ((size_t)(b * SS + _kb + st_r) * NKV + kvh) * 64 + st_c4; \
    const float* _vs = g_qkv + (size_t)(b * SS + _kb + st_r) * QKVLD + 1280 + kvh * HD + st_c4; \
    uint32_t _kd = smbase + ((bf) * TILEF + st_r * ATS + st_c4) * 4; \
    uint32_t _vd = smbase + ((2 + (bf)) * TILEF + st_r * ATS + st_c4) * 4; \
    _Pragma("unroll") \
    for (int _j = 0; _j < 4; _j++) { \
        cp_async16(_kd + _j * 16 * ATS * 4, _ks + (size_t)_j * 16 * NKV * 64); \
        cp_async16(_vd + _j * 16 * ATS * 4, _vs + (size_t)_j * 16 * QKVLD); \
    } \
    CP_COMMIT(); \
} while (0)

    AT_STAGE(t0, 0);

    for (int t = t0; t <= t1; t++) {
        int kb = t << 6;
        const int buf = (t - t0) & 1;
        CP_WAIT(0);
        __syncthreads();
        if (t < t1) AT_STAGE(t + 1, buf ^ 1);

        bool active = (kb <= q0 + wrow + 15) && (kb + 63 >= q0 + wrow - win + 1);
        if (active) {
            const uint32_t* Khl = Khl0 + buf * TILEF;
            const float* Vs = sm + (2 + buf) * TILEF;

            float accS[8][4] = {};
#pragma unroll
            for (int ks = 0; ks < 4; ks++) {
#pragma unroll
                for (int ni = 0; ni < 8; ni++) {
                    const uint32_t* kr = &Khl[(ni * 8 + gid) * ATS + ks * 8 + tig];
                    uint32_t bh2[2] = { kr[0],  kr[4] };
                    uint32_t bl2[2] = { kr[32], kr[36] };
                    mma_bf16(accS[ni], ahi[ks], bh2);
                    mma_bf16(accS[ni], alo[ks], bh2);
                    mma_bf16(accS[ni], ahi[ks], bl2);
                }
            }

            int qpos0 = q0 + wrow + gid;
            int qpos1 = qpos0 + 8;
            float mx0 = -1e30f, mx1 = -1e30f;
#pragma unroll
            for (int ni = 0; ni < 8; ni++) {
#pragma unroll
                for (int j = 0; j < 4; j++) {
                    int kpos = kb + ni * 8 + 2 * tig + (j & 1);
                    int qp = (j < 2) ? qpos0 : qpos1;
                    bool ok = (kpos <= qp) && (kpos >= qp - win + 1);
                    float s = ok ? accS[ni][j] : -1e30f;
                    accS[ni][j] = s;
                    if (j < 2) mx0 = fmaxf(mx0, s);
                    else       mx1 = fmaxf(mx1, s);
                }
            }
            mx0 = fmaxf(mx0, __shfl_xor_sync(0xffffffffu, mx0, 1));
            mx0 = fmaxf(mx0, __shfl_xor_sync(0xffffffffu, mx0, 2));
            mx1 = fmaxf(mx1, __shfl_xor_sync(0xffffffffu, mx1, 1));
            mx1 = fmaxf(mx1, __shfl_xor_sync(0xffffffffu, mx1, 2));

            float mnew0 = fmaxf(m0, mx0), mnew1 = fmaxf(m1, mx1);
            bool dead0 = (mnew0 <= -1e20f), dead1 = (mnew1 <= -1e20f);
            float scale0 = dead0 ? 1.f : __expf(m0 - mnew0);
            float scale1 = dead1 ? 1.f : __expf(m1 - mnew1);

            float rs0 = 0.f, rs1 = 0.f;
#pragma unroll
            for (int ni = 0; ni < 8; ni++) {
                int c0 = ni * 8 + 2 * tig;
#pragma unroll
                for (int j = 0; j < 4; j++) {
                    bool lo = (j < 2);
                    float p = lo ? (dead0 ? 0.f : __expf(accS[ni][j] - mnew0))
                                 : (dead1 ? 0.f : __expf(accS[ni][j] - mnew1));
                    if (lo) rs0 += p; else rs1 += p;
                    int row = lo ? (wrow + gid) : (wrow + gid + 8);
                    Ss[row * ATS + c0 + (j & 1)] = to_tf32(p);
                }
            }
            rs0 += __shfl_xor_sync(0xffffffffu, rs0, 1);
            rs0 += __shfl_xor_sync(0xffffffffu, rs0, 2);
            rs1 += __shfl_xor_sync(0xffffffffu, rs1, 1);
            rs1 += __shfl_xor_sync(0xffffffffu, rs1, 2);

            m0 = mnew0; m1 = mnew1;
            lsum0 = lsum0 * scale0 + rs0;
            lsum1 = lsum1 * scale1 + rs1;

#pragma unroll
            for (int ni = 0; ni < 8; ni++) {
                oacc[ni][0] *= scale0; oacc[ni][1] *= scale0;
                oacc[ni][2] *= scale1; oacc[ni][3] *= scale1;
            }
            __syncwarp();
#pragma unroll
            for (int ks = 0; ks < 8; ks++) {
                uint32_t pa[4];
                pa[0] = __float_as_uint(Ss[(wrow + gid) * ATS + ks * 8 + tig]);
                pa[1] = __float_as_uint(Ss[(wrow + gid + 8) * ATS + ks * 8 + tig]);
                pa[2] = __float_as_uint(Ss[(wrow + gid) * ATS + ks * 8 + tig + 4]);
                pa[3] = __float_as_uint(Ss[(wrow + gid + 8) * ATS + ks * 8 + tig + 4]);
#pragma unroll
                for (int ni = 0; ni < 8; ni++) {
                    uint32_t vb[2];
                    vb[0] = __float_as_uint(Vs[(ks * 8 + tig) * ATS + ni * 8 + gid]);
                    vb[1] = __float_as_uint(Vs[(ks * 8 + tig + 4) * ATS + ni * 8 + gid]);
                    mma_tf32(oacc[ni], pa, vb);
                }
            }
        }
    }

    float li0 = 1.f / lsum0;
    float li1 = 1.f / lsum1;

    __syncthreads();
#pragma unroll
    for (int ni = 0; ni < 8; ni++) {
        int c0 = ni * 8 + 2 * tig;
        Ss[(wrow + gid) * ATS + c0]         = oacc[ni][0] * li0;
        Ss[(wrow + gid) * ATS + c0 + 1]     = oacc[ni][1] * li0;
        Ss[(wrow + gid + 8) * ATS + c0]     = oacc[ni][2] * li1;
        Ss[(wrow + gid + 8) * ATS + c0 + 1] = oacc[ni][3] * li1;
    }
    __syncthreads();

    int rtile = b * 16 + qt;
#pragma unroll
    for (int tl = 0; tl < 4; tl++) {
        float* dtile = g_ya + ((size_t)rtile * 64 + h * 4 + tl) * 2048;
        for (int q = tid; q < 512; q += 256) {
            int gb = q >> 5;
            int g2 = gb >> 3, b2 = gb & 7;
            int ln = q & 31;
            int gd = ln >> 2, tg = ln & 3;
            const float* sp = &Ss[(b2 * 16 + gd) * ATS + tl * 16 + g2 * 8 + tg];
            float4 v;
            v.x = to_tf32(sp[0]);
            v.y = to_tf32(sp[8 * ATS]);
            v.z = to_tf32(sp[4]);
            v.w = to_tf32(sp[8 * ATS + 4]);
            *(float4*)(dtile + q * 4) = v;
        }
    }
}

// ---------------------------------------------------------------------------
extern "C" void kernel_launch(void* const* d_in, const int* in_sizes, int n_in,
                              void* d_out, int out_size)
{
    const float* x    = (const float*)d_in[0];
    const float* ve   = (const float*)d_in[1];
    const float* cosp = (const float*)d_in[2];
    const float* sinp = (const float*)d_in[3];
    const float* Wq   = (const float*)d_in[4];
    const float* Wk   = (const float*)d_in[5];
    const float* Wv   = (const float*)d_in[6];
    const float* Wo   = (const float*)d_in[7];
    const float* Wg   = (const float*)d_in[8];
    const int*   win  = (const int*)d_in[9];
    float* out = (float*)d_out;

    float *pqkv, *pqkv2, *pxa, *pya, *pwqkvT, *pwoT;
    cudaGetSymbolAddress((void**)&pqkv, g_qkv);
    cudaGetSymbolAddress((void**)&pqkv2, g_qkv2);
    cudaGetSymbolAddress((void**)&pxa, g_xa);
    cudaGetSymbolAddress((void**)&pya, g_ya);
    cudaGetSymbolAddress((void**)&pwqkvT, g_wqkvT);
    cudaGetSymbolAddress((void**)&pwoT, g_woT);

    // fragment-major packing (tf32 rounding folded in)
    pack_a<<<dim3(64, 32), 256>>>(x, pxa);
    pack_bqkv<<<dim3(64, 12), 256>>>(Wq, Wk, Wv, pwqkvT);
    pack_b<<<dim3(64, 8), 256>>>(Wo, pwoT, 1024, 0);

    cudaFuncSetAttribute(gemm_fm, cudaFuncAttributeMaxDynamicSharedMemorySize, GFM_SMEM);

    // fused QKV projection, split-K=2 (768 CTAs -> better wave packing)
    gemm_fm<<<dim3(12, 32, 2), 256, GFM_SMEM>>>(pxa, pwqkvT, pqkv, pqkv2, 32, QKVLD);

    // fused partial combine + v-gate + RoPE/RMSNorm + bf16 hi/lo packing
    prep_kernel<<<BB * SS * 6, 256>>>(cosp, sinp, x, ve, Wg);

    // flash attention (heavy-first order, register softmax)
    {
        int smem = (4 * TILEF + 128 * ATS) * sizeof(float);   // 104448 B
        cudaFuncSetAttribute(attn_tc, cudaFuncAttributeMaxDynamicSharedMemorySize, smem);
        attn_tc<<<BB * NH * (SS / 128), 256, smem>>>(win);
    }

    // output projection (single-K, reads fragment-major g_ya directly)
    gemm_fm<<<dim3(8, 32, 1), 256, GFM_SMEM>>>(pya, pwoT, out, nullptr, 64, DD);
}

// round 16
// speedup vs baseline: 1.1500x; 1.0164x over previous
#include <cuda_runtime.h>
#include <cuda_bf16.h>
#include <math.h>
#include <stdint.h>

#define BB 2
#define SS 2048
#define DD 1024
#define NH 16
#define NKV 4
#define HD 64
#define GATE_CH 12
#define EPSV 1e-6f
#define QKVLD 1536   // qkv buffer row stride: [q(1024) | k(256) | v(256)]

// ---------------- device scratch (allocation-free rule) ----------------
__device__ float    g_qkv[BB * SS * QKVLD];     // qkv partial 0 / combined v
__device__ float    g_qkv2[BB * SS * QKVLD];    // qkv partial 1
__device__ float    g_qkv3[BB * SS * QKVLD];    // qkv partial 2
__device__ float    g_xa[(size_t)32 * 64 * 2048];    // x, fragment-major A tiles
__device__ float    g_ya[(size_t)32 * 64 * 2048];    // attn out, fragment-major A tiles
__device__ float    g_wqkvT[(size_t)12 * 64 * 2048]; // Wq|Wk|Wv, fragment-major B tiles
__device__ float    g_woT[(size_t)8 * 64 * 2048];    // Wo, fragment-major B tiles
__device__ uint32_t g_qpk[BB * SS * NH * 64];   // q packed bf16 hi|lo
__device__ uint32_t g_kpk[BB * SS * NKV * 64];  // k packed bf16 hi|lo

// ---------------- helpers ----------------
__device__ __forceinline__ float to_tf32(float x) {
    float r; asm("cvt.rna.tf32.f32 %0, %1;" : "=f"(r) : "f"(x)); return r;
}
__device__ __forceinline__ uint32_t pack_bf16(float e, float o) {
    uint16_t a = __bfloat16_as_ushort(__float2bfloat16(e));
    uint16_t b = __bfloat16_as_ushort(__float2bfloat16(o));
    return ((uint32_t)b << 16) | a;
}
__device__ __forceinline__ void mma_tf32(float* d, const uint32_t* a, const uint32_t* b) {
    asm volatile(
        "mma.sync.aligned.m16n8k8.row.col.f32.tf32.tf32.f32 "
        "{%0,%1,%2,%3}, {%4,%5,%6,%7}, {%8,%9}, {%0,%1,%2,%3};\n"
        : "+f"(d[0]), "+f"(d[1]), "+f"(d[2]), "+f"(d[3])
        : "r"(a[0]), "r"(a[1]), "r"(a[2]), "r"(a[3]), "r"(b[0]), "r"(b[1]));
}
__device__ __forceinline__ void mma_bf16(float* d, const uint32_t* a, const uint32_t* b) {
    asm volatile(
        "mma.sync.aligned.m16n8k16.row.col.f32.bf16.bf16.f32 "
        "{%0,%1,%2,%3}, {%4,%5,%6,%7}, {%8,%9}, {%0,%1,%2,%3};\n"
        : "+f"(d[0]), "+f"(d[1]), "+f"(d[2]), "+f"(d[3])
        : "r"(a[0]), "r"(a[1]), "r"(a[2]), "r"(a[3]), "r"(b[0]), "r"(b[1]));
}
__device__ __forceinline__ void cp_async16(uint32_t saddr, const void* gptr) {
    asm volatile("cp.async.cg.shared.global [%0], [%1], 16;" :: "r"(saddr), "l"(gptr));
}
#define CP_COMMIT() asm volatile("cp.async.commit_group;")
#define CP_WAIT(n)  asm volatile("cp.async.wait_group %0;" :: "n"(n))

// ---------------------------------------------------------------------------
// pack_all: one launch for x (A tiles), Wq|Wk|Wv (B tiles), Wo (B tiles).
// grid (64, 52): ct<32 -> x row-tile ct; 32<=ct<44 -> qkv col-tile; ct>=44 -> Wo.
// ---------------------------------------------------------------------------
__global__ void pack_all(const float* __restrict__ x,
                         const float* __restrict__ Wq,
                         const float* __restrict__ Wk,
                         const float* __restrict__ Wv,
                         const float* __restrict__ Wo)
{
    int kt = blockIdx.x, ct = blockIdx.y;

    if (ct < 32) {
        // ---- pack_a: x row-tile rt = ct ----
        int rt = ct;
        float* dtile = g_xa + ((size_t)rt * 64 + kt) * 2048;
        const float* s = x + (size_t)rt * 128 * 1024 + kt * 16;
        for (int q = threadIdx.x; q < 512; q += 256) {
            int gb = q >> 5;
            int g = gb >> 3, b = gb & 7;
            int lane = q & 31;
            int gid = lane >> 2, tig = lane & 3;
            const float* p = s + (size_t)(b * 16 + gid) * 1024 + g * 8 + tig;
            float4 v;
            v.x = to_tf32(p[0]);
            v.y = to_tf32(p[8 * 1024]);
            v.z = to_tf32(p[4]);
            v.w = to_tf32(p[8 * 1024 + 4]);
            *(float4*)(dtile + q * 4) = v;
        }
        return;
    }

    // ---- pack_b: weight col tile ----
    const float* W;
    float* dst;
    int n_src, cl, dct;
    if (ct < 44) {
        dct = ct - 32;
        dst = g_wqkvT;
        if (dct < 8)       { W = Wq; n_src = 1024; cl = dct; }
        else if (dct < 10) { W = Wk; n_src = 256;  cl = dct - 8; }
        else               { W = Wv; n_src = 256;  cl = dct - 10; }
    } else {
        dct = ct - 44;
        dst = g_woT;
        W = Wo; n_src = 1024; cl = dct;
    }

    float* dtile = dst + ((size_t)dct * 64 + kt) * 2048;
    const float* s = W + (size_t)kt * 16 * n_src + cl * 128;
    for (int q = threadIdx.x; q < 512; q += 256) {
        int plane = q >> 8;
        int q8 = q & 255;
        int gw = q8 >> 5;
        int g = gw >> 2, w = gw & 3;
        int lane = q8 & 31;
        int gid = lane >> 2, tig = lane & 3;
        const float* p = s + (size_t)(g * 8 + tig + plane * 4) * n_src + w * 32 + gid;
        float4 v;
        v.x = to_tf32(p[0]);
        v.y = to_tf32(p[8]);
        v.z = to_tf32(p[16]);
        v.w = to_tf32(p[24]);
        *(float4*)(dtile + q * 4) = v;
    }
}

// ---------------------------------------------------------------------------
// gemm_fm<SPLITK>: tf32 HMMA GEMM on fragment-major tiles, BK=32 (pairs of
// k-tiles), 3-stage cp.async, single sync/iter. 32 pairs total split across
// SPLITK z-slices (11/11/10 for SPLITK=3).
// ---------------------------------------------------------------------------
#define GFM_SMEM 98304
template<int SPLITK>
__global__ __launch_bounds__(256, 2) void gemm_fm(
    const float* __restrict__ At, const float* __restrict__ Bt,
    float* __restrict__ C0, float* __restrict__ C1, float* __restrict__ C2,
    int ldc)
{
    extern __shared__ float smg[];
    uint32_t smb = (uint32_t)__cvta_generic_to_shared(smg);
    const int tid = threadIdx.x;
    const int lane = tid & 31, wid = tid >> 5;
    const int gid = lane >> 2, tig = lane & 3;
    const int wm4 = (wid >> 2) * 4;
    const int wn5 = wid & 3;
    const int rowBase = blockIdx.y * 128, colBase = blockIdx.x * 128;

    int pofs, np;
    float* C;
    if (SPLITK == 1) { pofs = 0; np = 32; C = C0; }
    else {
        int z = blockIdx.z;
        pofs = z * 11;
        np = (z == 2) ? 10 : 11;
        C = (z == 0) ? C0 : (z == 1) ? C1 : C2;
    }

    const float* Abase = At + ((size_t)blockIdx.y * 64 + pofs * 2) * 2048 + tid * 8;
    const float* Bbase = Bt + ((size_t)blockIdx.x * 64 + pofs * 2) * 2048 + tid * 8;

#define FM_STAGE(p, s) do { \
    uint32_t _d = smb + (s) * 32768 + tid * 32; \
    const float* _a = Abase + (size_t)(p) * 4096; \
    const float* _b = Bbase + (size_t)(p) * 4096; \
    cp_async16(_d,            _a);        cp_async16(_d + 16,           _a + 4); \
    cp_async16(_d + 8192,     _a + 2048); cp_async16(_d + 8192 + 16,    _a + 2052); \
    cp_async16(_d + 16384,    _b);        cp_async16(_d + 16384 + 16,   _b + 4); \
    cp_async16(_d + 24576,    _b + 2048); cp_async16(_d + 24576 + 16,   _b + 2052); \
    CP_COMMIT(); \
} while (0)

    FM_STAGE(0, 0);
    FM_STAGE(1, 1);

    float acc[4][4][4] = {};
    for (int it = 0; it < np; it++) {
        const int s = it % 3;
        if (it + 1 < np) { CP_WAIT(1); } else { CP_WAIT(0); }
        __syncthreads();
        if (it + 2 < np) FM_STAGE(it + 2, (it + 2) % 3);

#pragma unroll
        for (int t01 = 0; t01 < 2; t01++) {
            const uint4* As4 = (const uint4*)(smg + s * 8192 + t01 * 2048);
            const uint4* Bs4 = (const uint4*)(smg + s * 8192 + 4096 + t01 * 2048);
#pragma unroll
            for (int g = 0; g < 2; g++) {
                uint4 afr[4];
#pragma unroll
                for (int mi = 0; mi < 4; mi++)
                    afr[mi] = As4[(g * 8 + wm4 + mi) * 32 + lane];
                uint4 b0 = Bs4[(g * 4 + wn5) * 32 + lane];
                uint4 b1 = Bs4[256 + (g * 4 + wn5) * 32 + lane];
                uint32_t bf[4][2] = {
                    {b0.x, b1.x}, {b0.y, b1.y}, {b0.z, b1.z}, {b0.w, b1.w}};
#pragma unroll
                for (int mi = 0; mi < 4; mi++) {
                    const uint32_t* af = (const uint32_t*)&afr[mi];
#pragma unroll
                    for (int ni = 0; ni < 4; ni++)
                        mma_tf32(acc[mi][ni], af, bf[ni]);
                }
            }
        }
    }

    const int warp_m = wm4 * 16, warp_n = wn5 * 32;
#pragma unroll
    for (int mi = 0; mi < 4; mi++) {
#pragma unroll
        for (int ni = 0; ni < 4; ni++) {
            int row = rowBase + warp_m + mi * 16 + gid;
            int col = colBase + warp_n + ni * 8 + 2 * tig;
            *(float2*)(C + (size_t)row * ldc + col) =
                make_float2(acc[mi][ni][0], acc[mi][ni][1]);
            *(float2*)(C + (size_t)(row + 8) * ldc + col) =
                make_float2(acc[mi][ni][2], acc[mi][ni][3]);
        }
    }
}

// ---------------------------------------------------------------------------
// Fused prep (combines 3 split-K partials): rope reads p1+p2+p3; vgate writes
// combined v back into g_qkv. 256-thread blocks, 4 head-units per block.
// ---------------------------------------------------------------------------
__global__ void prep_kernel(const float* __restrict__ cosp,
                            const float* __restrict__ sinp,
                            const float* __restrict__ x,
                            const float* __restrict__ ve,
                            const float* __restrict__ Wg)
{
    int blk = blockIdx.x;
    int grp = blk % 6;
    int bs = blk / 6;
    int unit = threadIdx.x >> 6;
    int d = threadIdx.x & 63;
    int hh = grp * 4 + unit;

    if (hh >= NH + NKV) {
        int kvh = hh - (NH + NKV);
        const float* xr = x + (size_t)bs * DD;
        float g = 0.f;
#pragma unroll
        for (int c = 0; c < GATE_CH; c++) g += xr[c] * Wg[c * NKV + kvh];
        g = 3.f / (1.f + __expf(-g));
        size_t off = (size_t)bs * QKVLD + 1280 + kvh * HD + d;
        float v = g_qkv[off] + g_qkv2[off] + g_qkv3[off];
        g_qkv[off] = to_tf32(v + g * ve[(size_t)bs * (NKV * HD) + kvh * HD + d]);
        return;
    }

    int s = bs % SS;
    size_t base = (size_t)bs * QKVLD + ((hh < NH) ? hh * HD : 1024 + (hh - NH) * HD);

    int half = d & 31;
    float c  = cosp[s * 32 + half];
    float sn = sinp[s * 32 + half];
    float x1 = g_qkv[base + half]      + g_qkv2[base + half]      + g_qkv3[base + half];
    float x2 = g_qkv[base + half + 32] + g_qkv2[base + half + 32] + g_qkv3[base + half + 32];
    float rot = (d < 32) ? (x1 * c + x2 * sn) : (-x1 * sn + x2 * c);

    __shared__ float red[4][2];
    float v = rot * rot;
#pragma unroll
    for (int o = 16; o > 0; o >>= 1) v += __shfl_xor_sync(0xffffffffu, v, o);
    if ((d & 31) == 0) red[unit][d >> 5] = v;
    __syncthreads();
    float total = red[unit][0] + red[unit][1];
    float r = rsqrtf(total * (1.f / HD) + EPSV) * 1.2f;
    float val = rot * r;
    if (hh < NH) val *= 0.125f;

    float hif = __bfloat162float(__float2bfloat16(val));
    float lof = val - hif;
    float val_o = __shfl_down_sync(0xffffffffu, val, 1);
    float lof_o = __shfl_down_sync(0xffffffffu, lof, 1);

    if ((d & 1) == 0) {
        uint32_t hp = pack_bf16(val, val_o);
        uint32_t lp = pack_bf16(lof, lof_o);
        uint32_t* out = (hh < NH)
            ? &g_qpk[((size_t)bs * NH + hh) * 64]
            : &g_kpk[((size_t)bs * NKV + (hh - NH)) * 64];
        out[d >> 1]        = hp;
        out[32 + (d >> 1)] = lp;
    }
}

// ---------------------------------------------------------------------------
// Tensor-core flash attention, 128 queries/CTA, 8 warps, register softmax,
// heavy-first CTA order. (unchanged from R14)
// ---------------------------------------------------------------------------
#define ATS 68
#define TILEF (64 * ATS)
__global__ __launch_bounds__(256, 2) void attn_tc(const int* __restrict__ winp)
{
    const int win = *winp;
    int bid = blockIdx.x;
    int qt = 15 - (bid & 15);
    int bh = bid >> 4;
    int h = bh % NH;
    int b = bh / NH;
    int q0 = qt * 128;
    int kvh = h / (NH / NKV);

    const int tid = threadIdx.x;
    const int lane = tid & 31;
    const int warp = tid >> 5;
    const int wrow = warp * 16;
    const int gid = lane >> 2;
    const int tig = lane & 3;

    extern __shared__ float sm[];
    uint32_t* Khl0 = (uint32_t*)sm;
    float* Ss = sm + 4 * TILEF;
    uint32_t smbase = (uint32_t)__cvta_generic_to_shared(sm);

    const int st_r  = tid >> 4;
    const int st_c4 = (tid & 15) * 4;

    {
        uint32_t* Qs = (uint32_t*)Ss;
        for (int i = tid; i < 128 * 16; i += 256) {
            int r = i >> 4;
            int c4 = (i & 15) * 4;
            *(uint4*)&Qs[r * ATS + c4] =
                *(const uint4*)(g_qpk + ((size_t)(b * SS + q0 + r) * NH + h) * 64 + c4);
        }
    }
    __syncthreads();

    uint32_t ahi[4][4], alo[4][4];
    {
        const uint32_t* Qs = (const uint32_t*)Ss;
#pragma unroll
        for (int ks = 0; ks < 4; ks++) {
            int cb = ks * 8 + tig;
            ahi[ks][0] = Qs[(wrow + gid) * ATS + cb];
            ahi[ks][1] = Qs[(wrow + gid + 8) * ATS + cb];
            ahi[ks][2] = Qs[(wrow + gid) * ATS + cb + 4];
            ahi[ks][3] = Qs[(wrow + gid + 8) * ATS + cb + 4];
            alo[ks][0] = Qs[(wrow + gid) * ATS + 32 + cb];
            alo[ks][1] = Qs[(wrow + gid + 8) * ATS + 32 + cb];
            alo[ks][2] = Qs[(wrow + gid) * ATS + 32 + cb + 4];
            alo[ks][3] = Qs[(wrow + gid + 8) * ATS + 32 + cb + 4];
        }
    }

    float m0 = -1e30f, m1 = -1e30f, lsum0 = 0.f, lsum1 = 0.f;
    float oacc[8][4] = {};

    int kmin = q0 - win + 1;
    if (kmin < 0) kmin = 0;
    int t0 = kmin >> 6;
    int t1 = (q0 + 127) >> 6;

#define AT_STAGE(tt, bf) do { \
    int _kb = (tt) << 6; \
    const uint32_t* _ks = g_kpk + ((size_t)(b * SS + _kb + st_r) * NKV + kvh) * 64 + st_c4; \
    const float* _vs = g_qkv + (size_t)(b * SS + _kb + st_r) * QKVLD + 1280 + kvh * HD + st_c4; \
    uint32_t _kd = smbase + ((bf) * TILEF + st_r * ATS + st_c4) * 4; \
    uint32_t _vd = smbase + ((2 + (bf)) * TILEF + st_r * ATS + st_c4) * 4; \
    _Pragma("unroll") \
    for (int _j = 0; _j < 4; _j++) { \
        cp_async16(_kd + _j * 16 * ATS * 4, _ks + (size_t)_j * 16 * NKV * 64); \
        cp_async16(_vd + _j * 16 * ATS * 4, _vs + (size_t)_j * 16 * QKVLD); \
    } \
    CP_COMMIT(); \
} while (0)

    AT_STAGE(t0, 0);

    for (int t = t0; t <= t1; t++) {
        int kb = t << 6;
        const int buf = (t - t0) & 1;
        CP_WAIT(0);
        __syncthreads();
        if (t < t1) AT_STAGE(t + 1, buf ^ 1);

        bool active = (kb <= q0 + wrow + 15) && (kb + 63 >= q0 + wrow - win + 1);
        if (active) {
            const uint32_t* Khl = Khl0 + buf * TILEF;
            const float* Vs = sm + (2 + buf) * TILEF;

            float accS[8][4] = {};
#pragma unroll
            for (int ks = 0; ks < 4; ks++) {
#pragma unroll
                for (int ni = 0; ni < 8; ni++) {
                    const uint32_t* kr = &Khl[(ni * 8 + gid) * ATS + ks * 8 + tig];
                    uint32_t bh2[2] = { kr[0],  kr[4] };
                    uint32_t bl2[2] = { kr[32], kr[36] };
                    mma_bf16(accS[ni], ahi[ks], bh2);
                    mma_bf16(accS[ni], alo[ks], bh2);
                    mma_bf16(accS[ni], ahi[ks], bl2);
                }
            }

            int qpos0 = q0 + wrow + gid;
            int qpos1 = qpos0 + 8;
            float mx0 = -1e30f, mx1 = -1e30f;
#pragma unroll
            for (int ni = 0; ni < 8; ni++) {
#pragma unroll
                for (int j = 0; j < 4; j++) {
                    int kpos = kb + ni * 8 + 2 * tig + (j & 1);
                    int qp = (j < 2) ? qpos0 : qpos1;
                    bool ok = (kpos <= qp) && (kpos >= qp - win + 1);
                    float s = ok ? accS[ni][j] : -1e30f;
                    accS[ni][j] = s;
                    if (j < 2) mx0 = fmaxf(mx0, s);
                    else       mx1 = fmaxf(mx1, s);
                }
            }
            mx0 = fmaxf(mx0, __shfl_xor_sync(0xffffffffu, mx0, 1));
            mx0 = fmaxf(mx0, __shfl_xor_sync(0xffffffffu, mx0, 2));
            mx1 = fmaxf(mx1, __shfl_xor_sync(0xffffffffu, mx1, 1));
            mx1 = fmaxf(mx1, __shfl_xor_sync(0xffffffffu, mx1, 2));

            float mnew0 = fmaxf(m0, mx0), mnew1 = fmaxf(m1, mx1);
            bool dead0 = (mnew0 <= -1e20f), dead1 = (mnew1 <= -1e20f);
            float scale0 = dead0 ? 1.f : __expf(m0 - mnew0);
            float scale1 = dead1 ? 1.f : __expf(m1 - mnew1);

            float rs0 = 0.f, rs1 = 0.f;
#pragma unroll
            for (int ni = 0; ni < 8; ni++) {
                int c0 = ni * 8 + 2 * tig;
#pragma unroll
                for (int j = 0; j < 4; j++) {
                    bool lo = (j < 2);
                    float p = lo ? (dead0 ? 0.f : __expf(accS[ni][j] - mnew0))
                                 : (dead1 ? 0.f : __expf(accS[ni][j] - mnew1));
                    if (lo) rs0 += p; else rs1 += p;
                    int row = lo ? (wrow + gid) : (wrow + gid + 8);
                    Ss[row * ATS + c0 + (j & 1)] = to_tf32(p);
                }
            }
            rs0 += __shfl_xor_sync(0xffffffffu, rs0, 1);
            rs0 += __shfl_xor_sync(0xffffffffu, rs0, 2);
            rs1 += __shfl_xor_sync(0xffffffffu, rs1, 1);
            rs1 += __shfl_xor_sync(0xffffffffu, rs1, 2);

            m0 = mnew0; m1 = mnew1;
            lsum0 = lsum0 * scale0 + rs0;
            lsum1 = lsum1 * scale1 + rs1;

#pragma unroll
            for (int ni = 0; ni < 8; ni++) {
                oacc[ni][0] *= scale0; oacc[ni][1] *= scale0;
                oacc[ni][2] *= scale1; oacc[ni][3] *= scale1;
            }
            __syncwarp();
#pragma unroll
            for (int ks = 0; ks < 8; ks++) {
                uint32_t pa[4];
                pa[0] = __float_as_uint(Ss[(wrow + gid) * ATS + ks * 8 + tig]);
                pa[1] = __float_as_uint(Ss[(wrow + gid + 8) * ATS + ks * 8 + tig]);
                pa[2] = __float_as_uint(Ss[(wrow + gid) * ATS + ks * 8 + tig + 4]);
                pa[3] = __float_as_uint(Ss[(wrow + gid + 8) * ATS + ks * 8 + tig + 4]);
#pragma unroll
                for (int ni = 0; ni < 8; ni++) {
                    uint32_t vb[2];
                    vb[0] = __float_as_uint(Vs[(ks * 8 + tig) * ATS + ni * 8 + gid]);
                    vb[1] = __float_as_uint(Vs[(ks * 8 + tig + 4) * ATS + ni * 8 + gid]);
                    mma_tf32(oacc[ni], pa, vb);
                }
            }
        }
    }

    float li0 = 1.f / lsum0;
    float li1 = 1.f / lsum1;

    __syncthreads();
#pragma unroll
    for (int ni = 0; ni < 8; ni++) {
        int c0 = ni * 8 + 2 * tig;
        Ss[(wrow + gid) * ATS + c0]         = oacc[ni][0] * li0;
        Ss[(wrow + gid) * ATS + c0 + 1]     = oacc[ni][1] * li0;
        Ss[(wrow + gid + 8) * ATS + c0]     = oacc[ni][2] * li1;
        Ss[(wrow + gid + 8) * ATS + c0 + 1] = oacc[ni][3] * li1;
    }
    __syncthreads();

    int rtile = b * 16 + qt;
#pragma unroll
    for (int tl = 0; tl < 4; tl++) {
        float* dtile = g_ya + ((size_t)rtile * 64 + h * 4 + tl) * 2048;
        for (int q = tid; q < 512; q += 256) {
            int gb = q >> 5;
            int g2 = gb >> 3, b2 = gb & 7;
            int ln = q & 31;
            int gd = ln >> 2, tg = ln & 3;
            const float* sp = &Ss[(b2 * 16 + gd) * ATS + tl * 16 + g2 * 8 + tg];
            float4 v;
            v.x = to_tf32(sp[0]);
            v.y = to_tf32(sp[8 * ATS]);
            v.z = to_tf32(sp[4]);
            v.w = to_tf32(sp[8 * ATS + 4]);
            *(float4*)(dtile + q * 4) = v;
        }
    }
}

// ---------------------------------------------------------------------------
extern "C" void kernel_launch(void* const* d_in, const int* in_sizes, int n_in,
                              void* d_out, int out_size)
{
    const float* x    = (const float*)d_in[0];
    const float* ve   = (const float*)d_in[1];
    const float* cosp = (const float*)d_in[2];
    const float* sinp = (const float*)d_in[3];
    const float* Wq   = (const float*)d_in[4];
    const float* Wk   = (const float*)d_in[5];
    const float* Wv   = (const float*)d_in[6];
    const float* Wo   = (const float*)d_in[7];
    const float* Wg   = (const float*)d_in[8];
    const int*   win  = (const int*)d_in[9];
    float* out = (float*)d_out;

    float *pqkv, *pqkv2, *pqkv3, *pxa, *pya, *pwqkvT, *pwoT;
    cudaGetSymbolAddress((void**)&pqkv, g_qkv);
    cudaGetSymbolAddress((void**)&pqkv2, g_qkv2);
    cudaGetSymbolAddress((void**)&pqkv3, g_qkv3);
    cudaGetSymbolAddress((void**)&pxa, g_xa);
    cudaGetSymbolAddress((void**)&pya, g_ya);
    cudaGetSymbolAddress((void**)&pwqkvT, g_wqkvT);
    cudaGetSymbolAddress((void**)&pwoT, g_woT);

    // single merged packing launch
    pack_all<<<dim3(64, 52), 256>>>(x, Wq, Wk, Wv, Wo);

    cudaFuncSetAttribute(gemm_fm<3>, cudaFuncAttributeMaxDynamicSharedMemorySize, GFM_SMEM);
    cudaFuncSetAttribute(gemm_fm<1>, cudaFuncAttributeMaxDynamicSharedMemorySize, GFM_SMEM);

    // fused QKV projection, split-K=3 (1152 CTAs, makespan 1.33T)
    gemm_fm<3><<<dim3(12, 32, 3), 256, GFM_SMEM>>>(pxa, pwqkvT, pqkv, pqkv2, pqkv3, QKVLD);

    // fused partial combine + v-gate + RoPE/RMSNorm + bf16 hi/lo packing
    prep_kernel<<<BB * SS * 6, 256>>>(cosp, sinp, x, ve, Wg);

    // flash attention
    {
        int smem = (4 * TILEF + 128 * ATS) * sizeof(float);   // 104448 B
        cudaFuncSetAttribute(attn_tc, cudaFuncAttributeMaxDynamicSharedMemorySize, smem);
        attn_tc<<<BB * NH * (SS / 128), 256, smem>>>(win);
    }

    // output projection (single wave, reads fragment-major g_ya directly)
    gemm_fm<1><<<dim3(8, 32, 1), 256, GFM_SMEM>>>(pya, pwoT, out, nullptr, nullptr, DD);
}